// round 2
// baseline (speedup 1.0000x reference)
#include <cuda_runtime.h>
#include <cuda_bf16.h>
#include <math.h>

#define Nn 100000
#define Ee 3200000
#define FIN 512
#define Hh 64
#define Cc 40
#define RANK 1600000u   // E - int(E*0.5): 0-based index into ascending sort

// ---------------- scratch (device globals; no allocations allowed) -------------
__device__ float g_h1a[Nn*Hh];    // x @ w1
__device__ float g_agg1[Nn*Hh];   // propagate layer 1 accumulator -> h1 (after relu, in place)
__device__ float g_x2a[Nn*Cc];    // h1 @ w2
__device__ float g_x2[Nn*Cc];     // propagate layer 2 -> x2 (bias added in place)
__device__ float g_dis[Nn];       // deg_inv_sqrt
__device__ int   g_degcnt[Nn];
__device__ unsigned g_hist1[65536];
__device__ unsigned g_hist2[65536];
__device__ unsigned g_bin1, g_rank1;
__device__ float g_thresh;
__device__ double g_loss;
__device__ float g_inn[Nn];       // 1 / max(||x2_i||, eps)

// vector reduction (sm_90+): 4 floats per atomic transaction
__device__ __forceinline__ void red_add_v4(float* addr, float a, float b, float c, float d) {
    asm volatile("red.global.add.v4.f32 [%0], {%1, %2, %3, %4};"
                 :: "l"(addr), "f"(a), "f"(b), "f"(c), "f"(d) : "memory");
}

// ---------------- kernels -----------------------------------------------------

__global__ void k_zero() {
    int i = blockIdx.x * blockDim.x + threadIdx.x;
    int stride = gridDim.x * blockDim.x;
    for (int j = i; j < Nn; j += stride) g_degcnt[j] = 0;
    for (int j = i; j < 65536; j += stride) { g_hist1[j] = 0; g_hist2[j] = 0; }
    if (i == 0) g_loss = 0.0;
}

// degree count (dst) + pass-1 histogram of edge_weight top-16 bits
__global__ void k_deg_hist(const int* __restrict__ dst, const float* __restrict__ ew) {
    int e = blockIdx.x * blockDim.x + threadIdx.x;
    if (e >= Ee) return;
    atomicAdd(&g_degcnt[dst[e]], 1);
    unsigned u = __float_as_uint(ew[e]);   // weights in [0,1): bit order == value order
    atomicAdd(&g_hist1[u >> 16], 1u);
}

__global__ void k_dis() {
    int i = blockIdx.x * blockDim.x + threadIdx.x;
    if (i < Nn) g_dis[i] = rsqrtf((float)g_degcnt[i] + 1.0f);
}

// find bin containing rank R. pass 0: g_hist1, rank=RANK -> g_bin1/g_rank1.
// pass 1: g_hist2, rank=g_rank1 -> writes g_thresh directly.
// NOTE: histogram selected INSIDE the kernel — passing a __device__ symbol as a
// host-side kernel arg hands the kernel the HOST shadow address (and on GB300,
// ATS makes that a silently-readable garbage pointer instead of a fault).
__global__ void k_scan(int pass) {
    const unsigned* __restrict__ hist = (pass == 0) ? g_hist1 : g_hist2;
    __shared__ unsigned s[1024];
    int t = threadIdx.x;
    unsigned R = (pass == 0) ? RANK : g_rank1;
    unsigned base = t * 64, sum = 0;
    #pragma unroll 8
    for (int j = 0; j < 64; j++) sum += hist[base + j];
    s[t] = sum;
    __syncthreads();
    for (int off = 1; off < 1024; off <<= 1) {
        unsigned v = (t >= off) ? s[t - off] : 0u;
        __syncthreads();
        s[t] += v;
        __syncthreads();
    }
    unsigned incl = s[t];
    unsigned excl = incl - sum;
    if (R >= excl && R < incl) {
        unsigned P = excl;
        for (int j = 0; j < 64; j++) {
            unsigned c = hist[base + j];
            if (R < P + c) {
                if (pass == 0) { g_bin1 = base + j; g_rank1 = R - P; }
                else           { g_thresh = __uint_as_float((g_bin1 << 16) | (base + j)); }
                break;
            }
            P += c;
        }
    }
}

__global__ void k_hist2(const float* __restrict__ ew) {
    int e = blockIdx.x * blockDim.x + threadIdx.x;
    if (e >= Ee) return;
    unsigned u = __float_as_uint(ew[e]);
    if ((u >> 16) == g_bin1) atomicAdd(&g_hist2[u & 0xFFFFu], 1u);
}

// GEMM1: g_h1a[N,64] = x[N,512] @ w1[512,64].  BM=128, BK=16, 256 threads, 8x4/thread.
__global__ void k_gemm1(const float* __restrict__ x, const float* __restrict__ w1) {
    __shared__ float xs[16][132];
    __shared__ float ws[16][64];
    int tid = threadIdx.x;
    int row0 = blockIdx.x * 128;
    int tx = tid & 15, ty = tid >> 4;   // tx: 4 cols, ty: 8 rows
    float acc[8][4] = {};
    for (int k0 = 0; k0 < FIN; k0 += 16) {
        // x tile: 128 rows x 16 k  (512 float4 loads, 2 per thread)
        #pragma unroll
        for (int l = tid; l < 512; l += 256) {
            int r = l >> 2, kc = (l & 3) * 4;
            float4 v = make_float4(0.f, 0.f, 0.f, 0.f);
            if (row0 + r < Nn) v = *(const float4*)&x[(size_t)(row0 + r) * FIN + k0 + kc];
            xs[kc + 0][r] = v.x; xs[kc + 1][r] = v.y; xs[kc + 2][r] = v.z; xs[kc + 3][r] = v.w;
        }
        { // w tile: 16 x 64
            int r = tid >> 4, c = (tid & 15) * 4;
            float4 v = *(const float4*)&w1[(size_t)(k0 + r) * Hh + c];
            ws[r][c] = v.x; ws[r][c + 1] = v.y; ws[r][c + 2] = v.z; ws[r][c + 3] = v.w;
        }
        __syncthreads();
        #pragma unroll
        for (int k = 0; k < 16; k++) {
            float b0 = ws[k][tx * 4], b1 = ws[k][tx * 4 + 1], b2 = ws[k][tx * 4 + 2], b3 = ws[k][tx * 4 + 3];
            #pragma unroll
            for (int i = 0; i < 8; i++) {
                float a = xs[k][ty * 8 + i];
                acc[i][0] += a * b0; acc[i][1] += a * b1; acc[i][2] += a * b2; acc[i][3] += a * b3;
            }
        }
        __syncthreads();
    }
    #pragma unroll
    for (int i = 0; i < 8; i++) {
        int r = row0 + ty * 8 + i;
        if (r < Nn) {
            float4 v = make_float4(acc[i][0], acc[i][1], acc[i][2], acc[i][3]);
            *(float4*)&g_h1a[(size_t)r * Hh + tx * 4] = v;
        }
    }
}

// agg1 = h1a * dis^2 (self-loop term seeds the accumulator)
__global__ void k_init1() {
    int idx = blockIdx.x * blockDim.x + threadIdx.x;   // < N*H exactly
    int i = idx >> 6;
    float d = g_dis[i];
    g_agg1[idx] = g_h1a[idx] * d * d;
}

// edge scatter, layer 1: 16 threads per edge, 4 cols each, v4 atomic
__global__ void k_scatter1(const int* __restrict__ src, const int* __restrict__ dst) {
    unsigned idx = blockIdx.x * 256u + threadIdx.x;    // exactly E*16 threads
    int e = idx >> 4;
    int c = (idx & 15) << 2;
    int s = src[e], d = dst[e];
    float nrm = g_dis[s] * g_dis[d];
    float4 v = *(const float4*)&g_h1a[(size_t)s * Hh + c];
    red_add_v4(&g_agg1[(size_t)d * Hh + c], v.x * nrm, v.y * nrm, v.z * nrm, v.w * nrm);
}

__global__ void k_bias_relu(const float* __restrict__ b1) {
    int idx = blockIdx.x * blockDim.x + threadIdx.x;   // < N*H
    float v = g_agg1[idx] + b1[idx & 63];
    g_agg1[idx] = v > 0.f ? v : 0.f;
}

// GEMM2: g_x2a[N,40] = h1[N,64] @ w2[64,40].  16 rows per block, 640 threads.
__global__ void k_gemm2(const float* __restrict__ w2) {
    __shared__ float ws[Hh * Cc];   // 64*40
    __shared__ float hs[16][Hh];
    int tid = threadIdx.x;
    int row0 = blockIdx.x * 16;
    for (int i = tid; i < Hh * Cc; i += 640) ws[i] = w2[i];
    for (int i = tid; i < 16 * Hh; i += 640) {
        int r = i >> 6, k = i & 63;
        hs[r][k] = (row0 + r < Nn) ? g_agg1[(size_t)(row0 + r) * Hh + k] : 0.f;
    }
    __syncthreads();
    int r = tid / Cc, c = tid % Cc;
    float acc = 0.f;
    #pragma unroll
    for (int k = 0; k < Hh; k++) acc += hs[r][k] * ws[k * Cc + c];
    int rr = row0 + r;
    if (rr < Nn) g_x2a[(size_t)rr * Cc + c] = acc;
}

__global__ void k_init2() {
    int idx = blockIdx.x * blockDim.x + threadIdx.x;   // < N*C exactly
    int i = idx / Cc;
    float d = g_dis[i];
    g_x2[idx] = g_x2a[idx] * d * d;
}

// edge scatter, layer 2: 10 chunks of 4 cols per edge
__global__ void k_scatter2(const int* __restrict__ src, const int* __restrict__ dst) {
    unsigned idx = blockIdx.x * 256u + threadIdx.x;    // exactly E*10 threads
    int e = idx / 10u;
    int c = (idx - e * 10u) << 2;
    int s = src[e], d = dst[e];
    float nrm = g_dis[s] * g_dis[d];
    float4 v = *(const float4*)&g_x2a[(size_t)s * Cc + c];
    red_add_v4(&g_x2[(size_t)d * Cc + c], v.x * nrm, v.y * nrm, v.z * nrm, v.w * nrm);
}

__global__ void k_bias2(const float* __restrict__ b2) {
    int idx = blockIdx.x * blockDim.x + threadIdx.x;   // < N*C
    int c = idx % Cc;
    g_x2[idx] += b2[c];
}

__global__ void k_inn() {
    int i = blockIdx.x * blockDim.x + threadIdx.x;
    if (i >= Nn) return;
    const float* row = &g_x2[(size_t)i * Cc];
    float s = 0.f;
    #pragma unroll
    for (int c = 0; c < Cc; c++) { float v = row[c]; s += v * v; }
    float n = sqrtf(s);
    n = fmaxf(n, 1e-8f);
    g_inn[i] = 1.0f / n;
}

// log_softmax: warp per row (C=40: lane handles c=lane, and c=lane+32 for lane<8)
__global__ void k_lsm(float* __restrict__ out) {
    int w = blockIdx.x * 8 + (threadIdx.x >> 5);
    int lane = threadIdx.x & 31;
    if (w >= Nn) return;
    const float* row = &g_x2[(size_t)w * Cc];
    float v0 = row[lane];
    float v1 = (lane < 8) ? row[32 + lane] : -3.4e38f;
    float m = fmaxf(v0, v1);
    #pragma unroll
    for (int off = 16; off > 0; off >>= 1) m = fmaxf(m, __shfl_xor_sync(0xffffffffu, m, off));
    float s = expf(v0 - m) + ((lane < 8) ? expf(v1 - m) : 0.f);
    #pragma unroll
    for (int off = 16; off > 0; off >>= 1) s += __shfl_xor_sync(0xffffffffu, s, off);
    float ls = logf(s);
    out[(size_t)w * Cc + lane] = v0 - m - ls;
    if (lane < 8) out[(size_t)w * Cc + 32 + lane] = v1 - m - ls;
}

// loss: persistent grid, warp per edge (strided); ONE atomic per block.
#define LOSS_BLOCKS 2048
__global__ void k_loss(const int* __restrict__ src, const int* __restrict__ dst,
                       const float* __restrict__ ew, const float* __restrict__ lu) {
    __shared__ float sd[8];
    int wid = threadIdx.x >> 5, lane = threadIdx.x & 31;
    int warp_g = blockIdx.x * 8 + wid;
    int nwarp = LOSS_BLOCKS * 8;
    float thresh = g_thresh;
    float acc = 0.f;
    for (int e = warp_g; e < Ee; e += nwarp) {
        int s = src[e], d = dst[e];
        const float* a = &g_x2[(size_t)s * Cc];
        const float* b = &g_x2[(size_t)d * Cc];
        float dot = a[lane] * b[lane];
        if (lane < 8) dot += a[32 + lane] * b[32 + lane];
        #pragma unroll
        for (int off = 16; off > 0; off >>= 1) dot += __shfl_xor_sync(0xffffffffu, dot, off);
        if (lane == 0) {
            float cosv = dot * g_inn[s] * g_inn[d];
            float cs = 1.0f - cosv;
            float w = ew[e];
            bool m = (w >= thresh);
            float lp = m ? cs : (1.0f - cs);
            float le = m ? w : (1.0f - w);
            acc += le * lp * lu[e];
        }
    }
    if (lane == 0) sd[wid] = acc;
    __syncthreads();
    if (threadIdx.x == 0) {
        float t = 0.f;
        #pragma unroll
        for (int i = 0; i < 8; i++) t += sd[i];
        atomicAdd(&g_loss, (double)t);
    }
}

__global__ void k_final(float* __restrict__ out, int out_size) {
    if (out_size > Nn * Cc) out[Nn * Cc] = (float)(g_loss * (1.0 / (double)Ee));
}

// ---------------- launch ------------------------------------------------------

extern "C" void kernel_launch(void* const* d_in, const int* in_sizes, int n_in,
                              void* d_out, int out_size) {
    const float* x  = (const float*)d_in[0];
    const int*   ei = (const int*)d_in[1];
    const float* ew = (const float*)d_in[2];
    const float* lu = (const float*)d_in[3];
    const float* w1 = (const float*)d_in[4];
    const float* b1 = (const float*)d_in[5];
    const float* w2 = (const float*)d_in[6];
    const float* b2 = (const float*)d_in[7];
    const int* src = ei;
    const int* dst = ei + Ee;
    float* out = (float*)d_out;

    k_zero<<<256, 256>>>();
    k_deg_hist<<<(Ee + 255) / 256, 256>>>(dst, ew);
    k_dis<<<(Nn + 255) / 256, 256>>>();
    k_scan<<<1, 1024>>>(0);
    k_hist2<<<(Ee + 255) / 256, 256>>>(ew);
    k_scan<<<1, 1024>>>(1);

    k_gemm1<<<(Nn + 127) / 128, 256>>>(x, w1);
    k_init1<<<(Nn * Hh) / 256, 256>>>();
    k_scatter1<<<(Ee * 16) / 256, 256>>>(src, dst);
    k_bias_relu<<<(Nn * Hh) / 256, 256>>>(b1);

    k_gemm2<<<(Nn + 15) / 16, 640>>>(w2);
    k_init2<<<(Nn * Cc) / 256, 256>>>();
    k_scatter2<<<(Ee * 10) / 256, 256>>>(src, dst);
    k_bias2<<<(Nn * Cc) / 256, 256>>>(b2);

    k_inn<<<(Nn + 255) / 256, 256>>>();
    k_lsm<<<(Nn + 7) / 8, 256>>>(out);
    k_loss<<<LOSS_BLOCKS, 256>>>(src, dst, ew, lu);
    k_final<<<1, 1>>>(out, out_size);
}

// round 3
// speedup vs baseline: 1.1212x; 1.1212x over previous
#include <cuda_runtime.h>
#include <cuda_bf16.h>
#include <math.h>

#define Nn 100000
#define Ee 3200000
#define FIN 512
#define Hh 64
#define Cc 40
#define RANK 1600000u   // E - int(E*0.5): 0-based index into ascending sort

// ---------------- scratch (device globals; no allocations allowed) -------------
__device__ float g_h1a[Nn*Hh];    // x @ w1
__device__ float g_agg1[Nn*Hh];   // layer-1 accumulator (seeded with self-loop term)
__device__ float g_x2a[Nn*Cc];    // h1 @ w2
__device__ float g_x2[Nn*Cc];     // layer-2 accumulator -> x2 (bias added in k_post2)
__device__ __nv_bfloat162 g_x2n[Nn*20];  // normalized x2 rows, bf16 pairs (for loss)
__device__ float g_dis[Nn];       // deg_inv_sqrt
__device__ int   g_degcnt[Nn];
__device__ unsigned g_hist1[65536];
__device__ unsigned g_hist2[65536];
__device__ unsigned g_bin1, g_rank1;
__device__ float g_thresh;
__device__ double g_loss;

// vector reduction (sm_90+): 4 floats per atomic transaction
__device__ __forceinline__ void red_add_v4(float* addr, float a, float b, float c, float d) {
    asm volatile("red.global.add.v4.f32 [%0], {%1, %2, %3, %4};"
                 :: "l"(addr), "f"(a), "f"(b), "f"(c), "f"(d) : "memory");
}

// ---------------- kernels -----------------------------------------------------

__global__ void k_zero() {
    int i = blockIdx.x * blockDim.x + threadIdx.x;
    int stride = gridDim.x * blockDim.x;
    for (int j = i; j < Nn; j += stride) g_degcnt[j] = 0;
    for (int j = i; j < 65536; j += stride) { g_hist1[j] = 0; g_hist2[j] = 0; }
    if (i == 0) g_loss = 0.0;
}

// degree count (dst) + pass-1 histogram of edge_weight top-16 bits
__global__ void k_deg_hist(const int* __restrict__ dst, const float* __restrict__ ew) {
    int e = blockIdx.x * blockDim.x + threadIdx.x;
    if (e >= Ee) return;
    atomicAdd(&g_degcnt[dst[e]], 1);
    unsigned u = __float_as_uint(ew[e]);   // weights in [0,1): bit order == value order
    atomicAdd(&g_hist1[u >> 16], 1u);
}

__global__ void k_dis() {
    int i = blockIdx.x * blockDim.x + threadIdx.x;
    if (i < Nn) g_dis[i] = rsqrtf((float)g_degcnt[i] + 1.0f);
}

// find bin containing rank R. pass 0: g_hist1 -> g_bin1/g_rank1.  pass 1: g_hist2 -> g_thresh.
// Histogram selected INSIDE the kernel (host-side __device__ symbol arg = host shadow addr trap).
// uint4 loads: 16 LDG per thread instead of 64 (single-block kernel is LSU-issue-floor bound).
__global__ void k_scan(int pass) {
    const uint4* __restrict__ hist4 = (pass == 0) ? (const uint4*)g_hist1 : (const uint4*)g_hist2;
    const unsigned* __restrict__ hist = (pass == 0) ? g_hist1 : g_hist2;
    __shared__ unsigned s[1024];
    int t = threadIdx.x;
    unsigned R = (pass == 0) ? RANK : g_rank1;
    unsigned sum = 0;
    #pragma unroll
    for (int j = 0; j < 16; j++) {
        uint4 v = hist4[t * 16 + j];
        sum += v.x + v.y + v.z + v.w;
    }
    s[t] = sum;
    __syncthreads();
    for (int off = 1; off < 1024; off <<= 1) {
        unsigned v = (t >= off) ? s[t - off] : 0u;
        __syncthreads();
        s[t] += v;
        __syncthreads();
    }
    unsigned incl = s[t];
    unsigned excl = incl - sum;
    if (R >= excl && R < incl) {
        unsigned P = excl, base = t * 64;
        for (int j = 0; j < 64; j++) {
            unsigned c = hist[base + j];
            if (R < P + c) {
                if (pass == 0) { g_bin1 = base + j; g_rank1 = R - P; }
                else           { g_thresh = __uint_as_float((g_bin1 << 16) | (base + j)); }
                break;
            }
            P += c;
        }
    }
}

__global__ void k_hist2(const float* __restrict__ ew) {
    int e = blockIdx.x * blockDim.x + threadIdx.x;
    if (e >= Ee) return;
    unsigned u = __float_as_uint(ew[e]);
    if ((u >> 16) == g_bin1) atomicAdd(&g_hist2[u & 0xFFFFu], 1u);
}

// GEMM1: h1a[N,64] = x[N,512] @ w1[512,64]; epilogue also seeds agg1 = h1a*dis^2.
__global__ void k_gemm1(const float* __restrict__ x, const float* __restrict__ w1) {
    __shared__ float xs[16][132];
    __shared__ float ws[16][64];
    int tid = threadIdx.x;
    int row0 = blockIdx.x * 128;
    int tx = tid & 15, ty = tid >> 4;   // tx: 4 cols, ty: 8 rows
    float acc[8][4] = {};
    for (int k0 = 0; k0 < FIN; k0 += 16) {
        #pragma unroll
        for (int l = tid; l < 512; l += 256) {
            int r = l >> 2, kc = (l & 3) * 4;
            float4 v = make_float4(0.f, 0.f, 0.f, 0.f);
            if (row0 + r < Nn) v = *(const float4*)&x[(size_t)(row0 + r) * FIN + k0 + kc];
            xs[kc + 0][r] = v.x; xs[kc + 1][r] = v.y; xs[kc + 2][r] = v.z; xs[kc + 3][r] = v.w;
        }
        {
            int r = tid >> 4, c = (tid & 15) * 4;
            float4 v = *(const float4*)&w1[(size_t)(k0 + r) * Hh + c];
            ws[r][c] = v.x; ws[r][c + 1] = v.y; ws[r][c + 2] = v.z; ws[r][c + 3] = v.w;
        }
        __syncthreads();
        #pragma unroll
        for (int k = 0; k < 16; k++) {
            float b0 = ws[k][tx * 4], b1 = ws[k][tx * 4 + 1], b2 = ws[k][tx * 4 + 2], b3 = ws[k][tx * 4 + 3];
            #pragma unroll
            for (int i = 0; i < 8; i++) {
                float a = xs[k][ty * 8 + i];
                acc[i][0] += a * b0; acc[i][1] += a * b1; acc[i][2] += a * b2; acc[i][3] += a * b3;
            }
        }
        __syncthreads();
    }
    #pragma unroll
    for (int i = 0; i < 8; i++) {
        int r = row0 + ty * 8 + i;
        if (r < Nn) {
            float d = g_dis[r]; float d2 = d * d;
            float4 v = make_float4(acc[i][0], acc[i][1], acc[i][2], acc[i][3]);
            *(float4*)&g_h1a[(size_t)r * Hh + tx * 4] = v;
            float4 w = make_float4(v.x * d2, v.y * d2, v.z * d2, v.w * d2);
            *(float4*)&g_agg1[(size_t)r * Hh + tx * 4] = w;
        }
    }
}

// edge scatter, layer 1: 16 threads per edge, 4 cols each, v4 atomic
__global__ void k_scatter1(const int* __restrict__ src, const int* __restrict__ dst) {
    unsigned idx = blockIdx.x * 256u + threadIdx.x;    // exactly E*16 threads
    int e = idx >> 4;
    int c = (idx & 15) << 2;
    int s = src[e], d = dst[e];
    float nrm = g_dis[s] * g_dis[d];
    float4 v = *(const float4*)&g_h1a[(size_t)s * Hh + c];
    red_add_v4(&g_agg1[(size_t)d * Hh + c], v.x * nrm, v.y * nrm, v.z * nrm, v.w * nrm);
}

__global__ void k_bias_relu(const float* __restrict__ b1) {
    int idx = blockIdx.x * blockDim.x + threadIdx.x;   // < N*H
    float v = g_agg1[idx] + b1[idx & 63];
    g_agg1[idx] = v > 0.f ? v : 0.f;
}

// GEMM2: x2a[N,40] = h1[N,64] @ w2[64,40]; epilogue seeds g_x2 = x2a*dis^2.
__global__ void k_gemm2(const float* __restrict__ w2) {
    __shared__ float ws[Hh * Cc];
    __shared__ float hs[16][Hh];
    int tid = threadIdx.x;
    int row0 = blockIdx.x * 16;
    for (int i = tid; i < Hh * Cc; i += 640) ws[i] = w2[i];
    for (int i = tid; i < 16 * Hh; i += 640) {
        int r = i >> 6, k = i & 63;
        hs[r][k] = (row0 + r < Nn) ? g_agg1[(size_t)(row0 + r) * Hh + k] : 0.f;
    }
    __syncthreads();
    int r = tid / Cc, c = tid % Cc;
    float acc = 0.f;
    #pragma unroll
    for (int k = 0; k < Hh; k++) acc += hs[r][k] * ws[k * Cc + c];
    int rr = row0 + r;
    if (rr < Nn) {
        float d = g_dis[rr];
        g_x2a[(size_t)rr * Cc + c] = acc;
        g_x2[(size_t)rr * Cc + c] = acc * d * d;
    }
}

// edge scatter, layer 2: 10 chunks of 4 cols per edge
__global__ void k_scatter2(const int* __restrict__ src, const int* __restrict__ dst) {
    unsigned idx = blockIdx.x * 256u + threadIdx.x;    // exactly E*10 threads
    int e = idx / 10u;
    int c = (idx - e * 10u) << 2;
    int s = src[e], d = dst[e];
    float nrm = g_dis[s] * g_dis[d];
    float4 v = *(const float4*)&g_x2a[(size_t)s * Cc + c];
    red_add_v4(&g_x2[(size_t)d * Cc + c], v.x * nrm, v.y * nrm, v.z * nrm, v.w * nrm);
}

// post layer 2 (warp per row): x2 += b2 (in place), compute norm, write bf16 normalized row.
__global__ void k_post2(const float* __restrict__ b2) {
    int i = blockIdx.x * 8 + (threadIdx.x >> 5);
    int lane = threadIdx.x & 31;
    if (i >= Nn) return;
    float* row = &g_x2[(size_t)i * Cc];
    float v0 = 0.f, v1 = 0.f;
    if (lane < 20) {
        float2 v = *(const float2*)&row[lane * 2];
        v0 = v.x + b2[lane * 2];
        v1 = v.y + b2[lane * 2 + 1];
        *(float2*)&row[lane * 2] = make_float2(v0, v1);
    }
    float ss = v0 * v0 + v1 * v1;
    #pragma unroll
    for (int off = 16; off > 0; off >>= 1) ss += __shfl_xor_sync(0xffffffffu, ss, off);
    float inv = 1.0f / fmaxf(sqrtf(ss), 1e-8f);
    if (lane < 20) {
        g_x2n[(size_t)i * 20 + lane] = __floats2bfloat162_rn(v0 * inv, v1 * inv);
    }
}

// log_softmax: warp per row
__global__ void k_lsm(float* __restrict__ out) {
    int w = blockIdx.x * 8 + (threadIdx.x >> 5);
    int lane = threadIdx.x & 31;
    if (w >= Nn) return;
    const float* row = &g_x2[(size_t)w * Cc];
    float v0 = row[lane];
    float v1 = (lane < 8) ? row[32 + lane] : -3.4e38f;
    float m = fmaxf(v0, v1);
    #pragma unroll
    for (int off = 16; off > 0; off >>= 1) m = fmaxf(m, __shfl_xor_sync(0xffffffffu, m, off));
    float s = expf(v0 - m) + ((lane < 8) ? expf(v1 - m) : 0.f);
    #pragma unroll
    for (int off = 16; off > 0; off >>= 1) s += __shfl_xor_sync(0xffffffffu, s, off);
    float ls = logf(s);
    out[(size_t)w * Cc + lane] = v0 - m - ls;
    if (lane < 8) out[(size_t)w * Cc + 32 + lane] = v1 - m - ls;
}

// loss: persistent grid, warp per edge (strided); bf16 normalized rows -> dot == cos.
#define LOSS_BLOCKS 2048
__global__ void k_loss(const int* __restrict__ src, const int* __restrict__ dst,
                       const float* __restrict__ ew, const float* __restrict__ lu) {
    __shared__ float sd[8];
    int wid = threadIdx.x >> 5, lane = threadIdx.x & 31;
    int warp_g = blockIdx.x * 8 + wid;
    int nwarp = LOSS_BLOCKS * 8;
    float thresh = g_thresh;
    float acc = 0.f;
    for (int e = warp_g; e < Ee; e += nwarp) {
        int s = src[e], d = dst[e];
        float dot = 0.f;
        if (lane < 20) {
            __nv_bfloat162 a = g_x2n[(size_t)s * 20 + lane];
            __nv_bfloat162 b = g_x2n[(size_t)d * 20 + lane];
            float2 af = __bfloat1622float2(a);
            float2 bf = __bfloat1622float2(b);
            dot = af.x * bf.x + af.y * bf.y;
        }
        #pragma unroll
        for (int off = 16; off > 0; off >>= 1) dot += __shfl_xor_sync(0xffffffffu, dot, off);
        if (lane == 0) {
            float cs = 1.0f - dot;
            float w = ew[e];
            bool m = (w >= thresh);
            float lp = m ? cs : (1.0f - cs);
            float le = m ? w : (1.0f - w);
            acc += le * lp * lu[e];
        }
    }
    if (lane == 0) sd[wid] = acc;
    __syncthreads();
    if (threadIdx.x == 0) {
        float t = 0.f;
        #pragma unroll
        for (int i = 0; i < 8; i++) t += sd[i];
        atomicAdd(&g_loss, (double)t);
    }
}

__global__ void k_final(float* __restrict__ out, int out_size) {
    if (out_size > Nn * Cc) out[Nn * Cc] = (float)(g_loss * (1.0 / (double)Ee));
}

// ---------------- launch ------------------------------------------------------

extern "C" void kernel_launch(void* const* d_in, const int* in_sizes, int n_in,
                              void* d_out, int out_size) {
    const float* x  = (const float*)d_in[0];
    const int*   ei = (const int*)d_in[1];
    const float* ew = (const float*)d_in[2];
    const float* lu = (const float*)d_in[3];
    const float* w1 = (const float*)d_in[4];
    const float* b1 = (const float*)d_in[5];
    const float* w2 = (const float*)d_in[6];
    const float* b2 = (const float*)d_in[7];
    const int* src = ei;
    const int* dst = ei + Ee;
    float* out = (float*)d_out;

    k_zero<<<256, 256>>>();                              // 0
    k_deg_hist<<<(Ee + 255) / 256, 256>>>(dst, ew);      // 1
    k_dis<<<(Nn + 255) / 256, 256>>>();                  // 2
    k_gemm1<<<(Nn + 127) / 128, 256>>>(x, w1);           // 3 (fused agg1 seed)
    k_scan<<<1, 1024>>>(0);                              // 4
    k_scatter1<<<(Ee * 16) / 256, 256>>>(src, dst);      // 5  <- ncu -s 5 profiles this
    k_hist2<<<(Ee + 255) / 256, 256>>>(ew);              // 6
    k_scan<<<1, 1024>>>(1);                              // 7
    k_bias_relu<<<(Nn * Hh) / 256, 256>>>(b1);           // 8
    k_gemm2<<<(Nn + 15) / 16, 640>>>(w2);                // 9 (fused x2 seed)
    k_scatter2<<<(Ee * 10) / 256, 256>>>(src, dst);      // 10
    k_post2<<<(Nn + 7) / 8, 256>>>(b2);                  // 11 (bias + norm + bf16 rows)
    k_lsm<<<(Nn + 7) / 8, 256>>>(out);                   // 12
    k_loss<<<LOSS_BLOCKS, 256>>>(src, dst, ew, lu);      // 13
    k_final<<<1, 1>>>(out, out_size);                    // 14
}

// round 4
// speedup vs baseline: 1.2731x; 1.1355x over previous
#include <cuda_runtime.h>
#include <cuda_bf16.h>
#include <math.h>

#define Nn 100000
#define Ee 3200000
#define FIN 512
#define Hh 64
#define Cc 40
#define RANK 1600000u   // E - int(E*0.5): 0-based index into ascending sort

// ---------------- scratch (device globals; no allocations allowed) -------------
__device__ float g_h1a[Nn*Hh];    // x @ w1
__device__ float g_h1[Nn*Hh];     // propagated+relu'd layer-1 features
__device__ float g_x2a[Nn*Cc];    // h1 @ w2
__device__ __nv_bfloat162 g_x2n[Nn*20];  // normalized x2 rows, bf16 pairs (for loss)
__device__ float g_dis[Nn];       // deg_inv_sqrt
__device__ int   g_degcnt[Nn];
__device__ unsigned g_off[Nn + 1];  // CSR offsets (by dst)
__device__ int   g_cursor[Nn];
__device__ int2  g_csr[Ee];       // {src, norm-as-int} per edge, grouped by dst
__device__ unsigned g_hist1[65536];
__device__ unsigned g_hist2[65536];
__device__ unsigned g_bin1, g_rank1;
__device__ float g_thresh;
__device__ double g_loss;

// ---------------- kernels -----------------------------------------------------

__global__ void k_zero() {
    int i = blockIdx.x * blockDim.x + threadIdx.x;
    int stride = gridDim.x * blockDim.x;
    for (int j = i; j < Nn; j += stride) g_degcnt[j] = 0;
    for (int j = i; j < 65536; j += stride) { g_hist1[j] = 0; g_hist2[j] = 0; }
    if (i == 0) g_loss = 0.0;
}

// degree count (dst) + pass-1 histogram of edge_weight top-16 bits
__global__ void k_deg_hist(const int* __restrict__ dst, const float* __restrict__ ew) {
    int e = blockIdx.x * blockDim.x + threadIdx.x;
    if (e >= Ee) return;
    atomicAdd(&g_degcnt[dst[e]], 1);
    unsigned u = __float_as_uint(ew[e]);   // weights in [0,1): bit order == value order
    atomicAdd(&g_hist1[u >> 16], 1u);
}

__global__ void k_dis() {
    int i = blockIdx.x * blockDim.x + threadIdx.x;
    if (i < Nn) g_dis[i] = rsqrtf((float)g_degcnt[i] + 1.0f);
}

// single-block exclusive prefix over degcnt -> CSR offsets + cursors
#define PT 98   // 1024*98 >= Nn
__global__ void k_prefix() {
    __shared__ unsigned s[1024];
    int t = threadIdx.x;
    int base = t * PT;
    unsigned sum = 0;
    for (int j = 0; j < PT; j++) {
        int i = base + j;
        if (i < Nn) sum += (unsigned)g_degcnt[i];
    }
    s[t] = sum;
    __syncthreads();
    for (int off = 1; off < 1024; off <<= 1) {
        unsigned v = (t >= off) ? s[t - off] : 0u;
        __syncthreads();
        s[t] += v;
        __syncthreads();
    }
    unsigned run = s[t] - sum;   // exclusive
    for (int j = 0; j < PT; j++) {
        int i = base + j;
        if (i < Nn) {
            g_off[i] = run;
            g_cursor[i] = (int)run;
            run += (unsigned)g_degcnt[i];
        }
    }
    if (t == 1023) g_off[Nn] = s[1023];
}

// bucket edges by dst; store {src, norm}
__global__ void k_csr_fill(const int* __restrict__ src, const int* __restrict__ dst) {
    int e = blockIdx.x * blockDim.x + threadIdx.x;
    if (e >= Ee) return;
    int s = src[e], d = dst[e];
    float nrm = g_dis[s] * g_dis[d];
    int pos = atomicAdd(&g_cursor[d], 1);
    g_csr[pos] = make_int2(s, __float_as_int(nrm));
}

// find bin containing rank R. pass 0: g_hist1 -> g_bin1/g_rank1.  pass 1: g_hist2 -> g_thresh.
__global__ void k_scan(int pass) {
    const uint4* __restrict__ hist4 = (pass == 0) ? (const uint4*)g_hist1 : (const uint4*)g_hist2;
    const unsigned* __restrict__ hist = (pass == 0) ? g_hist1 : g_hist2;
    __shared__ unsigned s[1024];
    int t = threadIdx.x;
    unsigned R = (pass == 0) ? RANK : g_rank1;
    unsigned sum = 0;
    #pragma unroll
    for (int j = 0; j < 16; j++) {
        uint4 v = hist4[t * 16 + j];
        sum += v.x + v.y + v.z + v.w;
    }
    s[t] = sum;
    __syncthreads();
    for (int off = 1; off < 1024; off <<= 1) {
        unsigned v = (t >= off) ? s[t - off] : 0u;
        __syncthreads();
        s[t] += v;
        __syncthreads();
    }
    unsigned incl = s[t];
    unsigned excl = incl - sum;
    if (R >= excl && R < incl) {
        unsigned P = excl, base = t * 64;
        for (int j = 0; j < 64; j++) {
            unsigned c = hist[base + j];
            if (R < P + c) {
                if (pass == 0) { g_bin1 = base + j; g_rank1 = R - P; }
                else           { g_thresh = __uint_as_float((g_bin1 << 16) | (base + j)); }
                break;
            }
            P += c;
        }
    }
}

__global__ void k_hist2(const float* __restrict__ ew) {
    int e = blockIdx.x * blockDim.x + threadIdx.x;
    if (e >= Ee) return;
    unsigned u = __float_as_uint(ew[e]);
    if ((u >> 16) == g_bin1) atomicAdd(&g_hist2[u & 0xFFFFu], 1u);
}

// GEMM1: h1a[N,64] = x[N,512] @ w1[512,64]. 16B-aligned smem rows -> LDS.128.
__global__ void k_gemm1(const float* __restrict__ x, const float* __restrict__ w1) {
    __shared__ float xs[16][136];   // 136*4 = 544B row stride, 16B aligned
    __shared__ float ws[16][64];
    int tid = threadIdx.x;
    int row0 = blockIdx.x * 128;
    int tx = tid & 15, ty = tid >> 4;   // tx: 4 cols, ty: 8 rows
    float acc[8][4] = {};
    for (int k0 = 0; k0 < FIN; k0 += 16) {
        #pragma unroll
        for (int l = tid; l < 512; l += 256) {
            int r = l >> 2, kc = (l & 3) * 4;
            float4 v = make_float4(0.f, 0.f, 0.f, 0.f);
            if (row0 + r < Nn) v = *(const float4*)&x[(size_t)(row0 + r) * FIN + k0 + kc];
            xs[kc + 0][r] = v.x; xs[kc + 1][r] = v.y; xs[kc + 2][r] = v.z; xs[kc + 3][r] = v.w;
        }
        {
            int r = tid >> 4, c = (tid & 15) * 4;
            float4 v = *(const float4*)&w1[(size_t)(k0 + r) * Hh + c];
            *(float4*)&ws[r][c] = v;
        }
        __syncthreads();
        #pragma unroll
        for (int k = 0; k < 16; k++) {
            float4 b = *(const float4*)&ws[k][tx * 4];
            float4 a0 = *(const float4*)&xs[k][ty * 8];
            float4 a1 = *(const float4*)&xs[k][ty * 8 + 4];
            float av[8] = {a0.x, a0.y, a0.z, a0.w, a1.x, a1.y, a1.z, a1.w};
            #pragma unroll
            for (int i = 0; i < 8; i++) {
                acc[i][0] += av[i] * b.x; acc[i][1] += av[i] * b.y;
                acc[i][2] += av[i] * b.z; acc[i][3] += av[i] * b.w;
            }
        }
        __syncthreads();
    }
    #pragma unroll
    for (int i = 0; i < 8; i++) {
        int r = row0 + ty * 8 + i;
        if (r < Nn) {
            float4 v = make_float4(acc[i][0], acc[i][1], acc[i][2], acc[i][3]);
            *(float4*)&g_h1a[(size_t)r * Hh + tx * 4] = v;
        }
    }
}

// layer-1 aggregation via CSR gather: warp per node, lane owns float2 column.
// Fused: self-loop + bias + relu.
__global__ void k_gather1(const float* __restrict__ b1) {
    int i = blockIdx.x * 8 + (threadIdx.x >> 5);
    int lane = threadIdx.x & 31;
    if (i >= Nn) return;
    unsigned beg = g_off[i], end = g_off[i + 1];
    float d = g_dis[i]; float d2 = d * d;
    float2 acc = *(const float2*)&g_h1a[(size_t)i * Hh + 2 * lane];
    acc.x *= d2; acc.y *= d2;
    unsigned j = beg;
    for (; j + 2 <= end; j += 2) {
        int2 e0 = g_csr[j], e1 = g_csr[j + 1];
        float2 v0 = *(const float2*)&g_h1a[(size_t)e0.x * Hh + 2 * lane];
        float2 v1 = *(const float2*)&g_h1a[(size_t)e1.x * Hh + 2 * lane];
        float n0 = __int_as_float(e0.y), n1 = __int_as_float(e1.y);
        acc.x += v0.x * n0 + v1.x * n1;
        acc.y += v0.y * n0 + v1.y * n1;
    }
    if (j < end) {
        int2 e0 = g_csr[j];
        float2 v0 = *(const float2*)&g_h1a[(size_t)e0.x * Hh + 2 * lane];
        float n0 = __int_as_float(e0.y);
        acc.x += v0.x * n0; acc.y += v0.y * n0;
    }
    float2 bb = *(const float2*)&b1[2 * lane];
    acc.x = fmaxf(acc.x + bb.x, 0.f);
    acc.y = fmaxf(acc.y + bb.y, 0.f);
    *(float2*)&g_h1[(size_t)i * Hh + 2 * lane] = acc;
}

// GEMM2: x2a[N,40] = h1[N,64] @ w2[64,40]. 16 rows per block, 640 threads.
__global__ void k_gemm2(const float* __restrict__ w2) {
    __shared__ float ws[Hh * Cc];
    __shared__ float hs[16][Hh];
    int tid = threadIdx.x;
    int row0 = blockIdx.x * 16;
    for (int i = tid; i < Hh * Cc; i += 640) ws[i] = w2[i];
    for (int i = tid; i < 16 * Hh; i += 640) {
        int r = i >> 6, k = i & 63;
        hs[r][k] = (row0 + r < Nn) ? g_h1[(size_t)(row0 + r) * Hh + k] : 0.f;
    }
    __syncthreads();
    int r = tid / Cc, c = tid % Cc;
    float acc = 0.f;
    #pragma unroll
    for (int k = 0; k < Hh; k++) acc += hs[r][k] * ws[k * Cc + c];
    int rr = row0 + r;
    if (rr < Nn) g_x2a[(size_t)rr * Cc + c] = acc;
}

// layer-2 aggregation + bias + log_softmax + row-normalize (bf16), all fused.
// warp per node; lanes 0..19 each own a float2 column pair.
__global__ void k_gather2(const float* __restrict__ b2, float* __restrict__ out) {
    int i = blockIdx.x * 8 + (threadIdx.x >> 5);
    int lane = threadIdx.x & 31;
    if (i >= Nn) return;
    unsigned beg = g_off[i], end = g_off[i + 1];
    float d = g_dis[i]; float d2 = d * d;
    float2 acc = make_float2(0.f, 0.f);
    if (lane < 20) {
        acc = *(const float2*)&g_x2a[(size_t)i * Cc + 2 * lane];
        acc.x *= d2; acc.y *= d2;
    }
    unsigned j = beg;
    for (; j + 2 <= end; j += 2) {
        int2 e0 = g_csr[j], e1 = g_csr[j + 1];
        if (lane < 20) {
            float2 v0 = *(const float2*)&g_x2a[(size_t)e0.x * Cc + 2 * lane];
            float2 v1 = *(const float2*)&g_x2a[(size_t)e1.x * Cc + 2 * lane];
            float n0 = __int_as_float(e0.y), n1 = __int_as_float(e1.y);
            acc.x += v0.x * n0 + v1.x * n1;
            acc.y += v0.y * n0 + v1.y * n1;
        }
    }
    if (j < end) {
        int2 e0 = g_csr[j];
        if (lane < 20) {
            float2 v0 = *(const float2*)&g_x2a[(size_t)e0.x * Cc + 2 * lane];
            float n0 = __int_as_float(e0.y);
            acc.x += v0.x * n0; acc.y += v0.y * n0;
        }
    }
    if (lane < 20) {
        float2 bb = *(const float2*)&b2[2 * lane];
        acc.x += bb.x; acc.y += bb.y;
    }
    // log_softmax
    float m = (lane < 20) ? fmaxf(acc.x, acc.y) : -3.4e38f;
    #pragma unroll
    for (int off = 16; off > 0; off >>= 1) m = fmaxf(m, __shfl_xor_sync(0xffffffffu, m, off));
    float s = (lane < 20) ? (expf(acc.x - m) + expf(acc.y - m)) : 0.f;
    #pragma unroll
    for (int off = 16; off > 0; off >>= 1) s += __shfl_xor_sync(0xffffffffu, s, off);
    float ls = m + logf(s);
    if (lane < 20) {
        *(float2*)&out[(size_t)i * Cc + 2 * lane] = make_float2(acc.x - ls, acc.y - ls);
    }
    // normalized bf16 row for loss
    float ss = (lane < 20) ? (acc.x * acc.x + acc.y * acc.y) : 0.f;
    #pragma unroll
    for (int off = 16; off > 0; off >>= 1) ss += __shfl_xor_sync(0xffffffffu, ss, off);
    float inv = 1.0f / fmaxf(sqrtf(ss), 1e-8f);
    if (lane < 20) {
        g_x2n[(size_t)i * 20 + lane] = __floats2bfloat162_rn(acc.x * inv, acc.y * inv);
    }
}

// loss: persistent grid, warp per edge (strided); bf16 normalized rows -> dot == cos.
#define LOSS_BLOCKS 2048
__global__ void k_loss(const int* __restrict__ src, const int* __restrict__ dst,
                       const float* __restrict__ ew, const float* __restrict__ lu) {
    __shared__ float sd[8];
    int wid = threadIdx.x >> 5, lane = threadIdx.x & 31;
    int warp_g = blockIdx.x * 8 + wid;
    int nwarp = LOSS_BLOCKS * 8;
    float thresh = g_thresh;
    float acc = 0.f;
    for (int e = warp_g; e < Ee; e += nwarp) {
        int s = src[e], d = dst[e];
        float dot = 0.f;
        if (lane < 20) {
            float2 af = __bfloat1622float2(g_x2n[(size_t)s * 20 + lane]);
            float2 bf = __bfloat1622float2(g_x2n[(size_t)d * 20 + lane]);
            dot = af.x * bf.x + af.y * bf.y;
        }
        #pragma unroll
        for (int off = 16; off > 0; off >>= 1) dot += __shfl_xor_sync(0xffffffffu, dot, off);
        if (lane == 0) {
            float cs = 1.0f - dot;
            float w = ew[e];
            bool m = (w >= thresh);
            float lp = m ? cs : (1.0f - cs);
            float le = m ? w : (1.0f - w);
            acc += le * lp * lu[e];
        }
    }
    if (lane == 0) sd[wid] = acc;
    __syncthreads();
    if (threadIdx.x == 0) {
        float t = 0.f;
        #pragma unroll
        for (int i = 0; i < 8; i++) t += sd[i];
        atomicAdd(&g_loss, (double)t);
    }
}

__global__ void k_final(float* __restrict__ out, int out_size) {
    if (out_size > Nn * Cc) out[Nn * Cc] = (float)(g_loss * (1.0 / (double)Ee));
}

// ---------------- launch ------------------------------------------------------

extern "C" void kernel_launch(void* const* d_in, const int* in_sizes, int n_in,
                              void* d_out, int out_size) {
    const float* x  = (const float*)d_in[0];
    const int*   ei = (const int*)d_in[1];
    const float* ew = (const float*)d_in[2];
    const float* lu = (const float*)d_in[3];
    const float* w1 = (const float*)d_in[4];
    const float* b1 = (const float*)d_in[5];
    const float* w2 = (const float*)d_in[6];
    const float* b2 = (const float*)d_in[7];
    const int* src = ei;
    const int* dst = ei + Ee;
    float* out = (float*)d_out;

    k_zero<<<256, 256>>>();
    k_deg_hist<<<Ee / 256, 256>>>(dst, ew);
    k_dis<<<(Nn + 255) / 256, 256>>>();
    k_prefix<<<1, 1024>>>();
    k_csr_fill<<<Ee / 256, 256>>>(src, dst);
    k_gemm1<<<(Nn + 127) / 128, 256>>>(x, w1);
    k_scan<<<1, 1024>>>(0);
    k_hist2<<<Ee / 256, 256>>>(ew);
    k_scan<<<1, 1024>>>(1);
    k_gather1<<<(Nn + 7) / 8, 256>>>(b1);
    k_gemm2<<<(Nn + 15) / 16, 640>>>(w2);
    k_gather2<<<(Nn + 7) / 8, 256>>>(b2, out);
    k_loss<<<LOSS_BLOCKS, 256>>>(src, dst, ew, lu);
    k_final<<<1, 1>>>(out, out_size);
}

// round 5
// speedup vs baseline: 1.4465x; 1.1363x over previous
#include <cuda_runtime.h>
#include <cuda_bf16.h>
#include <math.h>

#define Nn 100000
#define Ee 3200000
#define FIN 512
#define Hh 64
#define Cc 40
#define RANK 1600000u   // E - int(E*0.5): 0-based index into ascending sort
#define PB 98           // prefix blocks: 98*1024 >= Nn

// ---------------- scratch (device globals; no allocations allowed) -------------
__device__ float g_h1a[Nn*Hh];    // (x @ w1) * dis  (pre-scaled rows)
__device__ float g_h1[Nn*Hh];     // propagated + relu'd layer-1 features
__device__ float g_x2a[Nn*Cc];    // (h1 @ w2) * dis (pre-scaled rows)
__device__ __nv_bfloat162 g_x2n[Nn*20];  // normalized x2 rows, bf16 pairs (for loss)
__device__ float g_dis[Nn];       // deg_inv_sqrt
__device__ int   g_degcnt[Nn];
__device__ unsigned g_off[Nn + 1];  // CSR offsets (by dst)
__device__ int   g_cursor[Nn];
__device__ int   g_csr[Ee];       // src per edge, grouped by dst (no norm needed!)
__device__ unsigned g_bsum[PB], g_bbase[PB];
__device__ unsigned g_hist1[65536];
__device__ unsigned g_hist2[65536];
__device__ unsigned g_bin1, g_rank1;
__device__ float g_thresh;
__device__ double g_loss;

// ---------------- kernels -----------------------------------------------------

__global__ void k_zero() {
    int i = blockIdx.x * blockDim.x + threadIdx.x;
    int stride = gridDim.x * blockDim.x;
    for (int j = i; j < Nn; j += stride) g_degcnt[j] = 0;
    for (int j = i; j < 65536; j += stride) { g_hist1[j] = 0; g_hist2[j] = 0; }
    if (i == 0) g_loss = 0.0;
}

// degree count (dst) + pass-1 histogram; 4 edges per thread, vector loads
__global__ void k_deg_hist(const int* __restrict__ dst, const float* __restrict__ ew) {
    int q = blockIdx.x * blockDim.x + threadIdx.x;   // < Ee/4
    int4 d = *(const int4*)&dst[q * 4];
    float4 w = *(const float4*)&ew[q * 4];
    atomicAdd(&g_degcnt[d.x], 1); atomicAdd(&g_degcnt[d.y], 1);
    atomicAdd(&g_degcnt[d.z], 1); atomicAdd(&g_degcnt[d.w], 1);
    atomicAdd(&g_hist1[__float_as_uint(w.x) >> 16], 1u);
    atomicAdd(&g_hist1[__float_as_uint(w.y) >> 16], 1u);
    atomicAdd(&g_hist1[__float_as_uint(w.z) >> 16], 1u);
    atomicAdd(&g_hist1[__float_as_uint(w.w) >> 16], 1u);
}

__global__ void k_dis() {
    int i = blockIdx.x * blockDim.x + threadIdx.x;
    if (i < Nn) g_dis[i] = rsqrtf((float)g_degcnt[i] + 1.0f);
}

// ---- coalesced 3-phase prefix sum over degcnt -> g_off / g_cursor ----
__global__ void k_psum() {
    __shared__ unsigned s[32];
    int t = threadIdx.x;
    int i = blockIdx.x * 1024 + t;
    unsigned v = (i < Nn) ? (unsigned)g_degcnt[i] : 0u;
    #pragma unroll
    for (int off = 16; off > 0; off >>= 1) v += __shfl_xor_sync(0xffffffffu, v, off);
    if ((t & 31) == 0) s[t >> 5] = v;
    __syncthreads();
    if (t < 32) {
        unsigned u = s[t];
        #pragma unroll
        for (int off = 16; off > 0; off >>= 1) u += __shfl_xor_sync(0xffffffffu, u, off);
        if (t == 0) g_bsum[blockIdx.x] = u;
    }
}

__global__ void k_bscan() {
    __shared__ unsigned s[128];
    int t = threadIdx.x;
    unsigned v = (t < PB) ? g_bsum[t] : 0u;
    s[t] = v;
    __syncthreads();
    for (int off = 1; off < 128; off <<= 1) {
        unsigned u = (t >= off) ? s[t - off] : 0u;
        __syncthreads();
        s[t] += u;
        __syncthreads();
    }
    if (t < PB) g_bbase[t] = s[t] - v;   // exclusive
    if (t == PB - 1) g_off[Nn] = s[t];   // total
}

__global__ void k_pwrite() {
    __shared__ unsigned s[1024];
    int t = threadIdx.x;
    int i = blockIdx.x * 1024 + t;
    unsigned v = (i < Nn) ? (unsigned)g_degcnt[i] : 0u;
    s[t] = v;
    __syncthreads();
    for (int off = 1; off < 1024; off <<= 1) {
        unsigned u = (t >= off) ? s[t - off] : 0u;
        __syncthreads();
        s[t] += u;
        __syncthreads();
    }
    unsigned excl = s[t] - v + g_bbase[blockIdx.x];
    if (i < Nn) { g_off[i] = excl; g_cursor[i] = (int)excl; }
}

// bucket edges by dst; store src only (norms folded into pre-scaled rows)
__global__ void k_csr_fill(const int* __restrict__ src, const int* __restrict__ dst) {
    int e = blockIdx.x * blockDim.x + threadIdx.x;
    if (e >= Ee) return;
    int pos = atomicAdd(&g_cursor[dst[e]], 1);
    g_csr[pos] = src[e];
}

// find bin containing rank R. pass 0: g_hist1 -> g_bin1/g_rank1.  pass 1: g_hist2 -> g_thresh.
__global__ void k_scan(int pass) {
    const uint4* __restrict__ hist4 = (pass == 0) ? (const uint4*)g_hist1 : (const uint4*)g_hist2;
    const unsigned* __restrict__ hist = (pass == 0) ? g_hist1 : g_hist2;
    __shared__ unsigned s[1024];
    int t = threadIdx.x;
    unsigned R = (pass == 0) ? RANK : g_rank1;
    unsigned sum = 0;
    #pragma unroll
    for (int j = 0; j < 16; j++) {
        uint4 v = hist4[t * 16 + j];
        sum += v.x + v.y + v.z + v.w;
    }
    s[t] = sum;
    __syncthreads();
    for (int off = 1; off < 1024; off <<= 1) {
        unsigned v = (t >= off) ? s[t - off] : 0u;
        __syncthreads();
        s[t] += v;
        __syncthreads();
    }
    unsigned incl = s[t];
    unsigned excl = incl - sum;
    if (R >= excl && R < incl) {
        unsigned P = excl, base = t * 64;
        for (int j = 0; j < 64; j++) {
            unsigned c = hist[base + j];
            if (R < P + c) {
                if (pass == 0) { g_bin1 = base + j; g_rank1 = R - P; }
                else           { g_thresh = __uint_as_float((g_bin1 << 16) | (base + j)); }
                break;
            }
            P += c;
        }
    }
}

__global__ void k_hist2(const float* __restrict__ ew) {
    int q = blockIdx.x * blockDim.x + threadIdx.x;   // < Ee/4
    float4 w = *(const float4*)&ew[q * 4];
    unsigned b = g_bin1;
    unsigned u0 = __float_as_uint(w.x), u1 = __float_as_uint(w.y);
    unsigned u2 = __float_as_uint(w.z), u3 = __float_as_uint(w.w);
    if ((u0 >> 16) == b) atomicAdd(&g_hist2[u0 & 0xFFFFu], 1u);
    if ((u1 >> 16) == b) atomicAdd(&g_hist2[u1 & 0xFFFFu], 1u);
    if ((u2 >> 16) == b) atomicAdd(&g_hist2[u2 & 0xFFFFu], 1u);
    if ((u3 >> 16) == b) atomicAdd(&g_hist2[u3 & 0xFFFFu], 1u);
}

// GEMM1: h1a[N,64] = (x[N,512] @ w1[512,64]) * dis.  LDS.128-friendly smem.
__global__ void k_gemm1(const float* __restrict__ x, const float* __restrict__ w1) {
    __shared__ float xs[16][136];   // 544B row stride, 16B aligned
    __shared__ float ws[16][64];
    int tid = threadIdx.x;
    int row0 = blockIdx.x * 128;
    int tx = tid & 15, ty = tid >> 4;
    float acc[8][4] = {};
    for (int k0 = 0; k0 < FIN; k0 += 16) {
        #pragma unroll
        for (int l = tid; l < 512; l += 256) {
            int r = l >> 2, kc = (l & 3) * 4;
            float4 v = make_float4(0.f, 0.f, 0.f, 0.f);
            if (row0 + r < Nn) v = *(const float4*)&x[(size_t)(row0 + r) * FIN + k0 + kc];
            xs[kc + 0][r] = v.x; xs[kc + 1][r] = v.y; xs[kc + 2][r] = v.z; xs[kc + 3][r] = v.w;
        }
        {
            int r = tid >> 4, c = (tid & 15) * 4;
            *(float4*)&ws[r][c] = *(const float4*)&w1[(size_t)(k0 + r) * Hh + c];
        }
        __syncthreads();
        #pragma unroll
        for (int k = 0; k < 16; k++) {
            float4 b = *(const float4*)&ws[k][tx * 4];
            float4 a0 = *(const float4*)&xs[k][ty * 8];
            float4 a1 = *(const float4*)&xs[k][ty * 8 + 4];
            float av[8] = {a0.x, a0.y, a0.z, a0.w, a1.x, a1.y, a1.z, a1.w};
            #pragma unroll
            for (int i = 0; i < 8; i++) {
                acc[i][0] += av[i] * b.x; acc[i][1] += av[i] * b.y;
                acc[i][2] += av[i] * b.z; acc[i][3] += av[i] * b.w;
            }
        }
        __syncthreads();
    }
    #pragma unroll
    for (int i = 0; i < 8; i++) {
        int r = row0 + ty * 8 + i;
        if (r < Nn) {
            float d = g_dis[r];
            float4 v = make_float4(acc[i][0] * d, acc[i][1] * d, acc[i][2] * d, acc[i][3] * d);
            *(float4*)&g_h1a[(size_t)r * Hh + tx * 4] = v;
        }
    }
}

// layer-1 aggregation: warp per node, lane owns float2 column.
// agg = dis_i * (Σ_j hs[j] + hs[i]);  + bias; relu.   (hs rows pre-scaled by dis)
__global__ void k_gather1(const float* __restrict__ b1) {
    int i = blockIdx.x * 8 + (threadIdx.x >> 5);
    int lane = threadIdx.x & 31;
    if (i >= Nn) return;
    unsigned beg = g_off[i], end = g_off[i + 1];
    float2 acc = *(const float2*)&g_h1a[(size_t)i * Hh + 2 * lane];  // self term
    unsigned j = beg;
    for (; j + 4 <= end; j += 4) {
        int s0 = g_csr[j], s1 = g_csr[j + 1], s2 = g_csr[j + 2], s3 = g_csr[j + 3];
        float2 v0 = *(const float2*)&g_h1a[(size_t)s0 * Hh + 2 * lane];
        float2 v1 = *(const float2*)&g_h1a[(size_t)s1 * Hh + 2 * lane];
        float2 v2 = *(const float2*)&g_h1a[(size_t)s2 * Hh + 2 * lane];
        float2 v3 = *(const float2*)&g_h1a[(size_t)s3 * Hh + 2 * lane];
        acc.x += (v0.x + v1.x) + (v2.x + v3.x);
        acc.y += (v0.y + v1.y) + (v2.y + v3.y);
    }
    for (; j < end; j++) {
        int s0 = g_csr[j];
        float2 v0 = *(const float2*)&g_h1a[(size_t)s0 * Hh + 2 * lane];
        acc.x += v0.x; acc.y += v0.y;
    }
    float d = g_dis[i];
    float2 bb = *(const float2*)&b1[2 * lane];
    acc.x = fmaxf(acc.x * d + bb.x, 0.f);
    acc.y = fmaxf(acc.y * d + bb.y, 0.f);
    *(float2*)&g_h1[(size_t)i * Hh + 2 * lane] = acc;
}

// GEMM2: x2a[N,40] = (h1[N,64] @ w2[64,40]) * dis.
__global__ void k_gemm2(const float* __restrict__ w2) {
    __shared__ float ws[Hh * Cc];
    __shared__ float hs[16][Hh];
    int tid = threadIdx.x;
    int row0 = blockIdx.x * 16;
    for (int i = tid; i < Hh * Cc; i += 640) ws[i] = w2[i];
    for (int i = tid; i < 16 * Hh; i += 640) {
        int r = i >> 6, k = i & 63;
        hs[r][k] = (row0 + r < Nn) ? g_h1[(size_t)(row0 + r) * Hh + k] : 0.f;
    }
    __syncthreads();
    int r = tid / Cc, c = tid % Cc;
    float acc = 0.f;
    #pragma unroll
    for (int k = 0; k < Hh; k++) acc += hs[r][k] * ws[k * Cc + c];
    int rr = row0 + r;
    if (rr < Nn) g_x2a[(size_t)rr * Cc + c] = acc * g_dis[rr];
}

// layer-2 aggregation + bias + log_softmax + row-normalize (bf16), all fused.
__global__ void k_gather2(const float* __restrict__ b2, float* __restrict__ out) {
    int i = blockIdx.x * 8 + (threadIdx.x >> 5);
    int lane = threadIdx.x & 31;
    if (i >= Nn) return;
    unsigned beg = g_off[i], end = g_off[i + 1];
    bool act = (lane < 20);
    float2 acc = make_float2(0.f, 0.f);
    if (act) acc = *(const float2*)&g_x2a[(size_t)i * Cc + 2 * lane];  // self term
    unsigned j = beg;
    for (; j + 4 <= end; j += 4) {
        int s0 = g_csr[j], s1 = g_csr[j + 1], s2 = g_csr[j + 2], s3 = g_csr[j + 3];
        if (act) {
            float2 v0 = *(const float2*)&g_x2a[(size_t)s0 * Cc + 2 * lane];
            float2 v1 = *(const float2*)&g_x2a[(size_t)s1 * Cc + 2 * lane];
            float2 v2 = *(const float2*)&g_x2a[(size_t)s2 * Cc + 2 * lane];
            float2 v3 = *(const float2*)&g_x2a[(size_t)s3 * Cc + 2 * lane];
            acc.x += (v0.x + v1.x) + (v2.x + v3.x);
            acc.y += (v0.y + v1.y) + (v2.y + v3.y);
        }
    }
    for (; j < end; j++) {
        int s0 = g_csr[j];
        if (act) {
            float2 v0 = *(const float2*)&g_x2a[(size_t)s0 * Cc + 2 * lane];
            acc.x += v0.x; acc.y += v0.y;
        }
    }
    float d = g_dis[i];
    if (act) {
        float2 bb = *(const float2*)&b2[2 * lane];
        acc.x = acc.x * d + bb.x;
        acc.y = acc.y * d + bb.y;
    }
    // log_softmax
    float m = act ? fmaxf(acc.x, acc.y) : -3.4e38f;
    #pragma unroll
    for (int off = 16; off > 0; off >>= 1) m = fmaxf(m, __shfl_xor_sync(0xffffffffu, m, off));
    float s = act ? (expf(acc.x - m) + expf(acc.y - m)) : 0.f;
    #pragma unroll
    for (int off = 16; off > 0; off >>= 1) s += __shfl_xor_sync(0xffffffffu, s, off);
    float ls = m + logf(s);
    if (act) *(float2*)&out[(size_t)i * Cc + 2 * lane] = make_float2(acc.x - ls, acc.y - ls);
    // normalized bf16 row for loss
    float ss = act ? (acc.x * acc.x + acc.y * acc.y) : 0.f;
    #pragma unroll
    for (int off = 16; off > 0; off >>= 1) ss += __shfl_xor_sync(0xffffffffu, ss, off);
    float inv = 1.0f / fmaxf(sqrtf(ss), 1e-8f);
    if (act) g_x2n[(size_t)i * 20 + lane] = __floats2bfloat162_rn(acc.x * inv, acc.y * inv);
}

// loss: persistent grid, warp per edge (strided); normalized rows -> dot == cos.
#define LOSS_BLOCKS 2048
__global__ void k_loss(const int* __restrict__ src, const int* __restrict__ dst,
                       const float* __restrict__ ew, const float* __restrict__ lu) {
    __shared__ float sd[8];
    int wid = threadIdx.x >> 5, lane = threadIdx.x & 31;
    int warp_g = blockIdx.x * 8 + wid;
    int nwarp = LOSS_BLOCKS * 8;
    float thresh = g_thresh;
    float acc = 0.f;
    for (int e = warp_g; e < Ee; e += nwarp) {
        int s = src[e], d = dst[e];
        float dot = 0.f;
        if (lane < 20) {
            float2 af = __bfloat1622float2(g_x2n[(size_t)s * 20 + lane]);
            float2 bf = __bfloat1622float2(g_x2n[(size_t)d * 20 + lane]);
            dot = af.x * bf.x + af.y * bf.y;
        }
        #pragma unroll
        for (int off = 16; off > 0; off >>= 1) dot += __shfl_xor_sync(0xffffffffu, dot, off);
        if (lane == 0) {
            float cs = 1.0f - dot;
            float w = ew[e];
            bool m = (w >= thresh);
            float lp = m ? cs : (1.0f - cs);
            float le = m ? w : (1.0f - w);
            acc += le * lp * lu[e];
        }
    }
    if (lane == 0) sd[wid] = acc;
    __syncthreads();
    if (threadIdx.x == 0) {
        float t = 0.f;
        #pragma unroll
        for (int i = 0; i < 8; i++) t += sd[i];
        atomicAdd(&g_loss, (double)t);
    }
}

__global__ void k_final(float* __restrict__ out, int out_size) {
    if (out_size > Nn * Cc) out[Nn * Cc] = (float)(g_loss * (1.0 / (double)Ee));
}

// ---------------- launch ------------------------------------------------------

extern "C" void kernel_launch(void* const* d_in, const int* in_sizes, int n_in,
                              void* d_out, int out_size) {
    const float* x  = (const float*)d_in[0];
    const int*   ei = (const int*)d_in[1];
    const float* ew = (const float*)d_in[2];
    const float* lu = (const float*)d_in[3];
    const float* w1 = (const float*)d_in[4];
    const float* b1 = (const float*)d_in[5];
    const float* w2 = (const float*)d_in[6];
    const float* b2 = (const float*)d_in[7];
    const int* src = ei;
    const int* dst = ei + Ee;
    float* out = (float*)d_out;

    k_zero<<<256, 256>>>();                              // 0
    k_deg_hist<<<Ee / 4 / 256, 256>>>(dst, ew);          // 1
    k_dis<<<(Nn + 255) / 256, 256>>>();                  // 2
    k_gemm1<<<(Nn + 127) / 128, 256>>>(x, w1);           // 3 <- profile slot
    k_psum<<<PB, 1024>>>();                              // 4
    k_bscan<<<1, 128>>>();                               // 5
    k_pwrite<<<PB, 1024>>>();                            // 6
    k_csr_fill<<<Ee / 256, 256>>>(src, dst);             // 7
    k_scan<<<1, 1024>>>(0);                              // 8
    k_hist2<<<Ee / 4 / 256, 256>>>(ew);                  // 9
    k_scan<<<1, 1024>>>(1);                              // 10
    k_gather1<<<(Nn + 7) / 8, 256>>>(b1);                // 11
    k_gemm2<<<(Nn + 15) / 16, 640>>>(w2);                // 12
    k_gather2<<<(Nn + 7) / 8, 256>>>(b2, out);           // 13
    k_loss<<<LOSS_BLOCKS, 256>>>(src, dst, ew, lu);      // 14
    k_final<<<1, 1>>>(out, out_size);                    // 15
}

// round 6
// speedup vs baseline: 1.5552x; 1.0751x over previous
#include <cuda_runtime.h>
#include <cuda_bf16.h>
#include <math.h>

#define Nn 100000
#define Ee 3200000
#define FIN 512
#define Hh 64
#define Cc 40
#define RANK 1600000u   // E - int(E*0.5): 0-based index into ascending sort
#define PB 98           // scan blocks: 98*1024 >= Nn

// ---------------- scratch (device globals; no allocations allowed) -------------
__device__ float g_h1a[Nn*Hh];    // (x @ w1) * dis  (pre-scaled rows)
__device__ float g_h1[Nn*Hh];     // propagated + relu'd layer-1 features
__device__ float g_x2a[Nn*Cc];    // (h1 @ w2) * dis (pre-scaled rows)
__device__ __nv_bfloat162 g_x2n[Nn*20];  // normalized x2 rows, bf16 pairs (for loss)
__device__ float g_dis[Nn];       // deg_inv_sqrt
__device__ int   g_degcnt[Nn];
__device__ unsigned g_off[Nn + 1];  // CSR offsets (by dst)
__device__ int   g_cursor[Nn];
__device__ int   g_csr[Ee];       // src per edge, grouped by dst
__device__ unsigned long long g_look[PB];  // decoupled-lookback state
__device__ unsigned g_hist1[65536];
__device__ unsigned g_hist2[65536];
__device__ unsigned g_bin1, g_rank1;
__device__ float g_thresh;
__device__ double g_loss;

// ---------------- kernels -----------------------------------------------------

__global__ void k_zero() {
    int i = blockIdx.x * blockDim.x + threadIdx.x;
    int stride = gridDim.x * blockDim.x;
    for (int j = i; j < Nn; j += stride) g_degcnt[j] = 0;
    for (int j = i; j < 65536; j += stride) { g_hist1[j] = 0; g_hist2[j] = 0; }
    if (i < PB) g_look[i] = 0ULL;
    if (i == 0) g_loss = 0.0;
}

// degree count (dst) + pass-1 histogram; 4 edges per thread, vector loads
__global__ void k_deg_hist(const int* __restrict__ dst, const float* __restrict__ ew) {
    int q = blockIdx.x * blockDim.x + threadIdx.x;   // < Ee/4
    int4 d = *(const int4*)&dst[q * 4];
    float4 w = *(const float4*)&ew[q * 4];
    atomicAdd(&g_degcnt[d.x], 1); atomicAdd(&g_degcnt[d.y], 1);
    atomicAdd(&g_degcnt[d.z], 1); atomicAdd(&g_degcnt[d.w], 1);
    atomicAdd(&g_hist1[__float_as_uint(w.x) >> 16], 1u);
    atomicAdd(&g_hist1[__float_as_uint(w.y) >> 16], 1u);
    atomicAdd(&g_hist1[__float_as_uint(w.z) >> 16], 1u);
    atomicAdd(&g_hist1[__float_as_uint(w.w) >> 16], 1u);
}

// single-pass decoupled-lookback prefix over degcnt -> g_off/g_cursor; also g_dis.
// status in bits[33:32]: 1 = aggregate ready, 2 = inclusive prefix ready.
__global__ void k_scanP() {
    __shared__ unsigned wsum[32];
    __shared__ unsigned sbase;
    int b = blockIdx.x, t = threadIdx.x;
    int i = b * 1024 + t;
    int lane = t & 31, w = t >> 5;
    unsigned deg = (i < Nn) ? (unsigned)g_degcnt[i] : 0u;
    // inclusive warp scan
    unsigned sv = deg;
    #pragma unroll
    for (int off = 1; off < 32; off <<= 1) {
        unsigned u = __shfl_up_sync(0xffffffffu, sv, off);
        if (lane >= off) sv += u;
    }
    if (lane == 31) wsum[w] = sv;
    __syncthreads();
    if (t < 32) {
        unsigned u = wsum[t];
        #pragma unroll
        for (int off = 1; off < 32; off <<= 1) {
            unsigned p = __shfl_up_sync(0xffffffffu, u, off);
            if (t >= off) u += p;
        }
        wsum[t] = u;
    }
    __syncthreads();
    unsigned incl = sv + (w ? wsum[w - 1] : 0u);
    unsigned total = wsum[31];
    if (t == 0) {
        if (b == 0) {
            atomicExch(&g_look[0], (2ULL << 32) | (unsigned long long)total);
            sbase = 0u;
        } else {
            atomicExch(&g_look[b], (1ULL << 32) | (unsigned long long)total);
            unsigned base = 0; int j = b - 1;
            while (true) {
                unsigned long long f = atomicAdd(&g_look[j], 0ULL);
                unsigned st = (unsigned)(f >> 32);
                if (st == 0) continue;
                base += (unsigned)f;
                if (st == 2) break;
                j--;
            }
            atomicExch(&g_look[b], (2ULL << 32) | (unsigned long long)(base + total));
            sbase = base;
        }
    }
    __syncthreads();
    if (i < Nn) {
        unsigned excl = sbase + incl - deg;
        g_off[i] = excl;
        g_cursor[i] = (int)excl;
        g_dis[i] = rsqrtf((float)deg + 1.0f);
        if (i == Nn - 1) g_off[Nn] = excl + deg;
    }
}

// bucket edges by dst; store src only (norms folded into pre-scaled rows)
__global__ void k_csr_fill(const int* __restrict__ src, const int* __restrict__ dst) {
    int e = blockIdx.x * blockDim.x + threadIdx.x;
    if (e >= Ee) return;
    int pos = atomicAdd(&g_cursor[dst[e]], 1);
    g_csr[pos] = src[e];
}

// find bin containing rank R. pass 0: g_hist1 -> g_bin1/g_rank1.  pass 1: g_hist2 -> g_thresh.
__global__ void k_scan(int pass) {
    const uint4* __restrict__ hist4 = (pass == 0) ? (const uint4*)g_hist1 : (const uint4*)g_hist2;
    const unsigned* __restrict__ hist = (pass == 0) ? g_hist1 : g_hist2;
    __shared__ unsigned s[1024];
    int t = threadIdx.x;
    unsigned R = (pass == 0) ? RANK : g_rank1;
    unsigned sum = 0;
    #pragma unroll
    for (int j = 0; j < 16; j++) {
        uint4 v = hist4[t * 16 + j];
        sum += v.x + v.y + v.z + v.w;
    }
    s[t] = sum;
    __syncthreads();
    for (int off = 1; off < 1024; off <<= 1) {
        unsigned v = (t >= off) ? s[t - off] : 0u;
        __syncthreads();
        s[t] += v;
        __syncthreads();
    }
    unsigned incl = s[t];
    unsigned excl = incl - sum;
    if (R >= excl && R < incl) {
        unsigned P = excl, base = t * 64;
        for (int j = 0; j < 64; j++) {
            unsigned c = hist[base + j];
            if (R < P + c) {
                if (pass == 0) { g_bin1 = base + j; g_rank1 = R - P; }
                else           { g_thresh = __uint_as_float((g_bin1 << 16) | (base + j)); }
                break;
            }
            P += c;
        }
    }
}

__global__ void k_hist2(const float* __restrict__ ew) {
    int q = blockIdx.x * blockDim.x + threadIdx.x;   // < Ee/4
    float4 w = *(const float4*)&ew[q * 4];
    unsigned b = g_bin1;
    unsigned u0 = __float_as_uint(w.x), u1 = __float_as_uint(w.y);
    unsigned u2 = __float_as_uint(w.z), u3 = __float_as_uint(w.w);
    if ((u0 >> 16) == b) atomicAdd(&g_hist2[u0 & 0xFFFFu], 1u);
    if ((u1 >> 16) == b) atomicAdd(&g_hist2[u1 & 0xFFFFu], 1u);
    if ((u2 >> 16) == b) atomicAdd(&g_hist2[u2 & 0xFFFFu], 1u);
    if ((u3 >> 16) == b) atomicAdd(&g_hist2[u3 & 0xFFFFu], 1u);
}

// GEMM1: h1a[N,64] = (x[N,512] @ w1[512,64]) * dis.
// 256x64 block tile, 256 threads, 8x8 micro-tile: 64 FFMA per 4 LDS.128.
__global__ void k_gemm1(const float* __restrict__ x, const float* __restrict__ w1) {
    __shared__ float xs[16][260];   // 256 rows + pad (1040B stride, 16B aligned)
    __shared__ float ws[16][64];
    int tid = threadIdx.x;
    int row0 = blockIdx.x * 256;
    int tx = tid & 7, ty = tid >> 3;   // tx: 8-col group, ty: 8-row group (0..31)
    float acc[8][8] = {};
    for (int k0 = 0; k0 < FIN; k0 += 16) {
        #pragma unroll
        for (int l = tid; l < 1024; l += 256) {
            int r = l >> 2, kc = (l & 3) * 4;
            float4 v = make_float4(0.f, 0.f, 0.f, 0.f);
            if (row0 + r < Nn) v = *(const float4*)&x[(size_t)(row0 + r) * FIN + k0 + kc];
            xs[kc + 0][r] = v.x; xs[kc + 1][r] = v.y; xs[kc + 2][r] = v.z; xs[kc + 3][r] = v.w;
        }
        {
            int r = tid >> 4, c = (tid & 15) * 4;
            *(float4*)&ws[r][c] = *(const float4*)&w1[(size_t)(k0 + r) * Hh + c];
        }
        __syncthreads();
        #pragma unroll
        for (int k = 0; k < 16; k++) {
            float4 b0 = *(const float4*)&ws[k][tx * 8];
            float4 b1 = *(const float4*)&ws[k][tx * 8 + 4];
            float4 a0 = *(const float4*)&xs[k][ty * 8];
            float4 a1 = *(const float4*)&xs[k][ty * 8 + 4];
            float av[8] = {a0.x, a0.y, a0.z, a0.w, a1.x, a1.y, a1.z, a1.w};
            float bv[8] = {b0.x, b0.y, b0.z, b0.w, b1.x, b1.y, b1.z, b1.w};
            #pragma unroll
            for (int ii = 0; ii < 8; ii++)
                #pragma unroll
                for (int jj = 0; jj < 8; jj++)
                    acc[ii][jj] += av[ii] * bv[jj];
        }
        __syncthreads();
    }
    #pragma unroll
    for (int ii = 0; ii < 8; ii++) {
        int r = row0 + ty * 8 + ii;
        if (r < Nn) {
            float d = g_dis[r];
            float4 v0 = make_float4(acc[ii][0] * d, acc[ii][1] * d, acc[ii][2] * d, acc[ii][3] * d);
            float4 v1 = make_float4(acc[ii][4] * d, acc[ii][5] * d, acc[ii][6] * d, acc[ii][7] * d);
            *(float4*)&g_h1a[(size_t)r * Hh + tx * 8] = v0;
            *(float4*)&g_h1a[(size_t)r * Hh + tx * 8 + 4] = v1;
        }
    }
}

// layer-1 aggregation: warp per node, lane owns float2 column.
__global__ void k_gather1(const float* __restrict__ b1) {
    int i = blockIdx.x * 8 + (threadIdx.x >> 5);
    int lane = threadIdx.x & 31;
    if (i >= Nn) return;
    unsigned beg = g_off[i], end = g_off[i + 1];
    float2 acc = *(const float2*)&g_h1a[(size_t)i * Hh + 2 * lane];  // self term
    unsigned j = beg;
    for (; j + 4 <= end; j += 4) {
        int s0 = g_csr[j], s1 = g_csr[j + 1], s2 = g_csr[j + 2], s3 = g_csr[j + 3];
        float2 v0 = *(const float2*)&g_h1a[(size_t)s0 * Hh + 2 * lane];
        float2 v1 = *(const float2*)&g_h1a[(size_t)s1 * Hh + 2 * lane];
        float2 v2 = *(const float2*)&g_h1a[(size_t)s2 * Hh + 2 * lane];
        float2 v3 = *(const float2*)&g_h1a[(size_t)s3 * Hh + 2 * lane];
        acc.x += (v0.x + v1.x) + (v2.x + v3.x);
        acc.y += (v0.y + v1.y) + (v2.y + v3.y);
    }
    for (; j < end; j++) {
        int s0 = g_csr[j];
        float2 v0 = *(const float2*)&g_h1a[(size_t)s0 * Hh + 2 * lane];
        acc.x += v0.x; acc.y += v0.y;
    }
    float d = g_dis[i];
    float2 bb = *(const float2*)&b1[2 * lane];
    acc.x = fmaxf(acc.x * d + bb.x, 0.f);
    acc.y = fmaxf(acc.y * d + bb.y, 0.f);
    *(float2*)&g_h1[(size_t)i * Hh + 2 * lane] = acc;
}

// GEMM2: x2a[N,40] = (h1[N,64] @ w2[64,40]) * dis.
__global__ void k_gemm2(const float* __restrict__ w2) {
    __shared__ float ws[Hh * Cc];
    __shared__ float hs[16][Hh];
    int tid = threadIdx.x;
    int row0 = blockIdx.x * 16;
    for (int i = tid; i < Hh * Cc; i += 640) ws[i] = w2[i];
    for (int i = tid; i < 16 * Hh; i += 640) {
        int r = i >> 6, k = i & 63;
        hs[r][k] = (row0 + r < Nn) ? g_h1[(size_t)(row0 + r) * Hh + k] : 0.f;
    }
    __syncthreads();
    int r = tid / Cc, c = tid % Cc;
    float acc = 0.f;
    #pragma unroll
    for (int k = 0; k < Hh; k++) acc += hs[r][k] * ws[k * Cc + c];
    int rr = row0 + r;
    if (rr < Nn) g_x2a[(size_t)rr * Cc + c] = acc * g_dis[rr];
}

// layer-2 aggregation + bias + log_softmax + row-normalize (bf16), all fused.
__global__ void k_gather2(const float* __restrict__ b2, float* __restrict__ out) {
    int i = blockIdx.x * 8 + (threadIdx.x >> 5);
    int lane = threadIdx.x & 31;
    if (i >= Nn) return;
    unsigned beg = g_off[i], end = g_off[i + 1];
    bool act = (lane < 20);
    float2 acc = make_float2(0.f, 0.f);
    if (act) acc = *(const float2*)&g_x2a[(size_t)i * Cc + 2 * lane];  // self term
    unsigned j = beg;
    for (; j + 4 <= end; j += 4) {
        int s0 = g_csr[j], s1 = g_csr[j + 1], s2 = g_csr[j + 2], s3 = g_csr[j + 3];
        if (act) {
            float2 v0 = *(const float2*)&g_x2a[(size_t)s0 * Cc + 2 * lane];
            float2 v1 = *(const float2*)&g_x2a[(size_t)s1 * Cc + 2 * lane];
            float2 v2 = *(const float2*)&g_x2a[(size_t)s2 * Cc + 2 * lane];
            float2 v3 = *(const float2*)&g_x2a[(size_t)s3 * Cc + 2 * lane];
            acc.x += (v0.x + v1.x) + (v2.x + v3.x);
            acc.y += (v0.y + v1.y) + (v2.y + v3.y);
        }
    }
    for (; j < end; j++) {
        int s0 = g_csr[j];
        if (act) {
            float2 v0 = *(const float2*)&g_x2a[(size_t)s0 * Cc + 2 * lane];
            acc.x += v0.x; acc.y += v0.y;
        }
    }
    float d = g_dis[i];
    if (act) {
        float2 bb = *(const float2*)&b2[2 * lane];
        acc.x = acc.x * d + bb.x;
        acc.y = acc.y * d + bb.y;
    }
    // log_softmax
    float m = act ? fmaxf(acc.x, acc.y) : -3.4e38f;
    #pragma unroll
    for (int off = 16; off > 0; off >>= 1) m = fmaxf(m, __shfl_xor_sync(0xffffffffu, m, off));
    float s = act ? (expf(acc.x - m) + expf(acc.y - m)) : 0.f;
    #pragma unroll
    for (int off = 16; off > 0; off >>= 1) s += __shfl_xor_sync(0xffffffffu, s, off);
    float ls = m + logf(s);
    if (act) *(float2*)&out[(size_t)i * Cc + 2 * lane] = make_float2(acc.x - ls, acc.y - ls);
    // normalized bf16 row for loss
    float ss = act ? (acc.x * acc.x + acc.y * acc.y) : 0.f;
    #pragma unroll
    for (int off = 16; off > 0; off >>= 1) ss += __shfl_xor_sync(0xffffffffu, ss, off);
    float inv = 1.0f / fmaxf(sqrtf(ss), 1e-8f);
    if (act) g_x2n[(size_t)i * 20 + lane] = __floats2bfloat162_rn(acc.x * inv, acc.y * inv);
}

// loss: persistent grid, warp per edge, 2-edge unroll for MLP.
#define LOSS_BLOCKS 2048
__global__ void k_loss(const int* __restrict__ src, const int* __restrict__ dst,
                       const float* __restrict__ ew, const float* __restrict__ lu) {
    __shared__ float sd[8];
    int wid = threadIdx.x >> 5, lane = threadIdx.x & 31;
    int warp_g = blockIdx.x * 8 + wid;
    int nwarp = LOSS_BLOCKS * 8;
    float thresh = g_thresh;
    bool act = (lane < 20);
    float acc = 0.f;
    int e = warp_g;
    for (; e + nwarp < Ee; e += 2 * nwarp) {
        int e2 = e + nwarp;
        int sA = src[e], dA = dst[e];
        int sB = src[e2], dB = dst[e2];
        float dotA = 0.f, dotB = 0.f;
        if (act) {
            float2 a0 = __bfloat1622float2(g_x2n[(size_t)sA * 20 + lane]);
            float2 b0 = __bfloat1622float2(g_x2n[(size_t)dA * 20 + lane]);
            float2 a1 = __bfloat1622float2(g_x2n[(size_t)sB * 20 + lane]);
            float2 b1 = __bfloat1622float2(g_x2n[(size_t)dB * 20 + lane]);
            dotA = a0.x * b0.x + a0.y * b0.y;
            dotB = a1.x * b1.x + a1.y * b1.y;
        }
        #pragma unroll
        for (int off = 16; off > 0; off >>= 1) {
            dotA += __shfl_xor_sync(0xffffffffu, dotA, off);
            dotB += __shfl_xor_sync(0xffffffffu, dotB, off);
        }
        if (lane == 0) {
            float wA = ew[e], wB = ew[e2];
            float csA = 1.0f - dotA, csB = 1.0f - dotB;
            bool mA = (wA >= thresh), mB = (wB >= thresh);
            acc += (mA ? wA : 1.0f - wA) * (mA ? csA : 1.0f - csA) * lu[e];
            acc += (mB ? wB : 1.0f - wB) * (mB ? csB : 1.0f - csB) * lu[e2];
        }
    }
    if (e < Ee) {
        int sA = src[e], dA = dst[e];
        float dotA = 0.f;
        if (act) {
            float2 a0 = __bfloat1622float2(g_x2n[(size_t)sA * 20 + lane]);
            float2 b0 = __bfloat1622float2(g_x2n[(size_t)dA * 20 + lane]);
            dotA = a0.x * b0.x + a0.y * b0.y;
        }
        #pragma unroll
        for (int off = 16; off > 0; off >>= 1) dotA += __shfl_xor_sync(0xffffffffu, dotA, off);
        if (lane == 0) {
            float wA = ew[e];
            float csA = 1.0f - dotA;
            bool mA = (wA >= thresh);
            acc += (mA ? wA : 1.0f - wA) * (mA ? csA : 1.0f - csA) * lu[e];
        }
    }
    if (lane == 0) sd[wid] = acc;
    __syncthreads();
    if (threadIdx.x == 0) {
        float t = 0.f;
        #pragma unroll
        for (int i = 0; i < 8; i++) t += sd[i];
        atomicAdd(&g_loss, (double)t);
    }
}

__global__ void k_final(float* __restrict__ out, int out_size) {
    if (out_size > Nn * Cc) out[Nn * Cc] = (float)(g_loss * (1.0 / (double)Ee));
}

// ---------------- launch ------------------------------------------------------

extern "C" void kernel_launch(void* const* d_in, const int* in_sizes, int n_in,
                              void* d_out, int out_size) {
    const float* x  = (const float*)d_in[0];
    const int*   ei = (const int*)d_in[1];
    const float* ew = (const float*)d_in[2];
    const float* lu = (const float*)d_in[3];
    const float* w1 = (const float*)d_in[4];
    const float* b1 = (const float*)d_in[5];
    const float* w2 = (const float*)d_in[6];
    const float* b2 = (const float*)d_in[7];
    const int* src = ei;
    const int* dst = ei + Ee;
    float* out = (float*)d_out;

    k_zero<<<256, 256>>>();                              // 0
    k_deg_hist<<<Ee / 4 / 256, 256>>>(dst, ew);          // 1
    k_scanP<<<PB, 1024>>>();                             // 2 (prefix + cursors + dis)
    k_csr_fill<<<Ee / 256, 256>>>(src, dst);             // 3 <- profile slot
    k_gemm1<<<(Nn + 255) / 256, 256>>>(x, w1);           // 4
    k_scan<<<1, 1024>>>(0);                              // 5
    k_hist2<<<Ee / 4 / 256, 256>>>(ew);                  // 6
    k_scan<<<1, 1024>>>(1);                              // 7
    k_gather1<<<(Nn + 7) / 8, 256>>>(b1);                // 8
    k_gemm2<<<(Nn + 15) / 16, 640>>>(w2);                // 9
    k_gather2<<<(Nn + 7) / 8, 256>>>(b2, out);           // 10
    k_loss<<<LOSS_BLOCKS, 256>>>(src, dst, ew, lu);      // 11
    k_final<<<1, 1>>>(out, out_size);                    // 12
}

// round 7
// speedup vs baseline: 1.6503x; 1.0612x over previous
#include <cuda_runtime.h>
#include <cuda_bf16.h>
#include <math.h>

#define Nn 100000
#define Ee 3200000
#define FIN 512
#define Hh 64
#define Cc 40
#define RANK 1600000u   // E - int(E*0.5): 0-based index into ascending sort
#define PB 98           // scan blocks: 98*1024 >= Nn

// ---------------- scratch (device globals; no allocations allowed) -------------
__device__ float g_h1a[Nn*Hh];    // (x @ w1) * dis  (pre-scaled rows)
__device__ float g_h1[Nn*Hh];     // propagated + relu'd layer-1 features
__device__ float g_x2a[Nn*Cc];    // (h1 @ w2) * dis (pre-scaled rows)
__device__ __nv_bfloat162 g_x2n[Nn*20];  // normalized x2 rows, bf16 pairs (for loss)
__device__ float g_dis[Nn];       // deg_inv_sqrt
__device__ int   g_degcnt[Nn];
__device__ unsigned g_off[Nn + 1];  // CSR offsets (by dst)
__device__ int   g_cursor[Nn];
__device__ int   g_csr[Ee];       // src per edge, grouped by dst
__device__ unsigned long long g_look[PB];  // decoupled-lookback state
__device__ unsigned g_hist1[65536];
__device__ unsigned g_hist2[65536];
__device__ unsigned g_bin1, g_rank1;
__device__ float g_thresh;
__device__ double g_loss;

// ---------------- kernels -----------------------------------------------------

__global__ void k_zero() {
    int i = blockIdx.x * blockDim.x + threadIdx.x;
    int stride = gridDim.x * blockDim.x;
    for (int j = i; j < Nn; j += stride) g_degcnt[j] = 0;
    for (int j = i; j < 65536; j += stride) { g_hist1[j] = 0; g_hist2[j] = 0; }
    if (i < PB) g_look[i] = 0ULL;
    if (i == 0) g_loss = 0.0;
}

// degree count (dst) + pass-1 histogram; 4 edges per thread, vector loads
__global__ void k_deg_hist(const int* __restrict__ dst, const float* __restrict__ ew) {
    int q = blockIdx.x * blockDim.x + threadIdx.x;   // < Ee/4
    int4 d = *(const int4*)&dst[q * 4];
    float4 w = *(const float4*)&ew[q * 4];
    atomicAdd(&g_degcnt[d.x], 1); atomicAdd(&g_degcnt[d.y], 1);
    atomicAdd(&g_degcnt[d.z], 1); atomicAdd(&g_degcnt[d.w], 1);
    atomicAdd(&g_hist1[__float_as_uint(w.x) >> 16], 1u);
    atomicAdd(&g_hist1[__float_as_uint(w.y) >> 16], 1u);
    atomicAdd(&g_hist1[__float_as_uint(w.z) >> 16], 1u);
    atomicAdd(&g_hist1[__float_as_uint(w.w) >> 16], 1u);
}

// single-pass decoupled-lookback prefix over degcnt -> g_off/g_cursor; also g_dis.
__global__ void k_scanP() {
    __shared__ unsigned wsum[32];
    __shared__ unsigned sbase;
    int b = blockIdx.x, t = threadIdx.x;
    int i = b * 1024 + t;
    int lane = t & 31, w = t >> 5;
    unsigned deg = (i < Nn) ? (unsigned)g_degcnt[i] : 0u;
    unsigned sv = deg;
    #pragma unroll
    for (int off = 1; off < 32; off <<= 1) {
        unsigned u = __shfl_up_sync(0xffffffffu, sv, off);
        if (lane >= off) sv += u;
    }
    if (lane == 31) wsum[w] = sv;
    __syncthreads();
    if (t < 32) {
        unsigned u = wsum[t];
        #pragma unroll
        for (int off = 1; off < 32; off <<= 1) {
            unsigned p = __shfl_up_sync(0xffffffffu, u, off);
            if (t >= off) u += p;
        }
        wsum[t] = u;
    }
    __syncthreads();
    unsigned incl = sv + (w ? wsum[w - 1] : 0u);
    unsigned total = wsum[31];
    if (t == 0) {
        if (b == 0) {
            atomicExch(&g_look[0], (2ULL << 32) | (unsigned long long)total);
            sbase = 0u;
        } else {
            atomicExch(&g_look[b], (1ULL << 32) | (unsigned long long)total);
            unsigned base = 0; int j = b - 1;
            while (true) {
                unsigned long long f = atomicAdd(&g_look[j], 0ULL);
                unsigned st = (unsigned)(f >> 32);
                if (st == 0) continue;
                base += (unsigned)f;
                if (st == 2) break;
                j--;
            }
            atomicExch(&g_look[b], (2ULL << 32) | (unsigned long long)(base + total));
            sbase = base;
        }
    }
    __syncthreads();
    if (i < Nn) {
        unsigned excl = sbase + incl - deg;
        g_off[i] = excl;
        g_cursor[i] = (int)excl;
        g_dis[i] = rsqrtf((float)deg + 1.0f);
        if (i == Nn - 1) g_off[Nn] = excl + deg;
    }
}

// bucket edges by dst; store src only
__global__ void k_csr_fill(const int* __restrict__ src, const int* __restrict__ dst) {
    int e = blockIdx.x * blockDim.x + threadIdx.x;
    if (e >= Ee) return;
    int pos = atomicAdd(&g_cursor[dst[e]], 1);
    g_csr[pos] = src[e];
}

// find bin containing rank R. pass 0: g_hist1 -> g_bin1/g_rank1.  pass 1: g_hist2 -> g_thresh.
__global__ void k_scan(int pass) {
    const uint4* __restrict__ hist4 = (pass == 0) ? (const uint4*)g_hist1 : (const uint4*)g_hist2;
    const unsigned* __restrict__ hist = (pass == 0) ? g_hist1 : g_hist2;
    __shared__ unsigned s[1024];
    int t = threadIdx.x;
    unsigned R = (pass == 0) ? RANK : g_rank1;
    unsigned sum = 0;
    #pragma unroll
    for (int j = 0; j < 16; j++) {
        uint4 v = hist4[t * 16 + j];
        sum += v.x + v.y + v.z + v.w;
    }
    s[t] = sum;
    __syncthreads();
    for (int off = 1; off < 1024; off <<= 1) {
        unsigned v = (t >= off) ? s[t - off] : 0u;
        __syncthreads();
        s[t] += v;
        __syncthreads();
    }
    unsigned incl = s[t];
    unsigned excl = incl - sum;
    if (R >= excl && R < incl) {
        unsigned P = excl, base = t * 64;
        for (int j = 0; j < 64; j++) {
            unsigned c = hist[base + j];
            if (R < P + c) {
                if (pass == 0) { g_bin1 = base + j; g_rank1 = R - P; }
                else           { g_thresh = __uint_as_float((g_bin1 << 16) | (base + j)); }
                break;
            }
            P += c;
        }
    }
}

__global__ void k_hist2(const float* __restrict__ ew) {
    int q = blockIdx.x * blockDim.x + threadIdx.x;   // < Ee/4
    float4 w = *(const float4*)&ew[q * 4];
    unsigned b = g_bin1;
    unsigned u0 = __float_as_uint(w.x), u1 = __float_as_uint(w.y);
    unsigned u2 = __float_as_uint(w.z), u3 = __float_as_uint(w.w);
    if ((u0 >> 16) == b) atomicAdd(&g_hist2[u0 & 0xFFFFu], 1u);
    if ((u1 >> 16) == b) atomicAdd(&g_hist2[u1 & 0xFFFFu], 1u);
    if ((u2 >> 16) == b) atomicAdd(&g_hist2[u2 & 0xFFFFu], 1u);
    if ((u3 >> 16) == b) atomicAdd(&g_hist2[u3 & 0xFFFFu], 1u);
}

// GEMM1: h1a[N,64] = (x[N,512] @ w1[512,64]) * dis.  256x64 tile, 8x8 micro-tile.
__global__ void k_gemm1(const float* __restrict__ x, const float* __restrict__ w1) {
    __shared__ float xs[16][260];
    __shared__ float ws[16][64];
    int tid = threadIdx.x;
    int row0 = blockIdx.x * 256;
    int tx = tid & 7, ty = tid >> 3;
    float acc[8][8] = {};
    for (int k0 = 0; k0 < FIN; k0 += 16) {
        #pragma unroll
        for (int l = tid; l < 1024; l += 256) {
            int r = l >> 2, kc = (l & 3) * 4;
            float4 v = make_float4(0.f, 0.f, 0.f, 0.f);
            if (row0 + r < Nn) v = *(const float4*)&x[(size_t)(row0 + r) * FIN + k0 + kc];
            xs[kc + 0][r] = v.x; xs[kc + 1][r] = v.y; xs[kc + 2][r] = v.z; xs[kc + 3][r] = v.w;
        }
        {
            int r = tid >> 4, c = (tid & 15) * 4;
            *(float4*)&ws[r][c] = *(const float4*)&w1[(size_t)(k0 + r) * Hh + c];
        }
        __syncthreads();
        #pragma unroll
        for (int k = 0; k < 16; k++) {
            float4 b0 = *(const float4*)&ws[k][tx * 8];
            float4 b1 = *(const float4*)&ws[k][tx * 8 + 4];
            float4 a0 = *(const float4*)&xs[k][ty * 8];
            float4 a1 = *(const float4*)&xs[k][ty * 8 + 4];
            float av[8] = {a0.x, a0.y, a0.z, a0.w, a1.x, a1.y, a1.z, a1.w};
            float bv[8] = {b0.x, b0.y, b0.z, b0.w, b1.x, b1.y, b1.z, b1.w};
            #pragma unroll
            for (int ii = 0; ii < 8; ii++)
                #pragma unroll
                for (int jj = 0; jj < 8; jj++)
                    acc[ii][jj] += av[ii] * bv[jj];
        }
        __syncthreads();
    }
    #pragma unroll
    for (int ii = 0; ii < 8; ii++) {
        int r = row0 + ty * 8 + ii;
        if (r < Nn) {
            float d = g_dis[r];
            float4 v0 = make_float4(acc[ii][0] * d, acc[ii][1] * d, acc[ii][2] * d, acc[ii][3] * d);
            float4 v1 = make_float4(acc[ii][4] * d, acc[ii][5] * d, acc[ii][6] * d, acc[ii][7] * d);
            *(float4*)&g_h1a[(size_t)r * Hh + tx * 8] = v0;
            *(float4*)&g_h1a[(size_t)r * Hh + tx * 8 + 4] = v1;
        }
    }
}

// layer-1 aggregation: warp per node, lane owns float2 column. 8-deep MLP.
__global__ void k_gather1(const float* __restrict__ b1) {
    int i = blockIdx.x * 8 + (threadIdx.x >> 5);
    int lane = threadIdx.x & 31;
    if (i >= Nn) return;
    unsigned beg = g_off[i], end = g_off[i + 1];
    float2 acc = *(const float2*)&g_h1a[(size_t)i * Hh + 2 * lane];  // self term
    float2 acc2 = make_float2(0.f, 0.f);
    unsigned j = beg;
    for (; j + 8 <= end; j += 8) {
        int s0 = g_csr[j],     s1 = g_csr[j + 1], s2 = g_csr[j + 2], s3 = g_csr[j + 3];
        int s4 = g_csr[j + 4], s5 = g_csr[j + 5], s6 = g_csr[j + 6], s7 = g_csr[j + 7];
        float2 v0 = *(const float2*)&g_h1a[(size_t)s0 * Hh + 2 * lane];
        float2 v1 = *(const float2*)&g_h1a[(size_t)s1 * Hh + 2 * lane];
        float2 v2 = *(const float2*)&g_h1a[(size_t)s2 * Hh + 2 * lane];
        float2 v3 = *(const float2*)&g_h1a[(size_t)s3 * Hh + 2 * lane];
        float2 v4 = *(const float2*)&g_h1a[(size_t)s4 * Hh + 2 * lane];
        float2 v5 = *(const float2*)&g_h1a[(size_t)s5 * Hh + 2 * lane];
        float2 v6 = *(const float2*)&g_h1a[(size_t)s6 * Hh + 2 * lane];
        float2 v7 = *(const float2*)&g_h1a[(size_t)s7 * Hh + 2 * lane];
        acc.x  += (v0.x + v1.x) + (v2.x + v3.x);
        acc.y  += (v0.y + v1.y) + (v2.y + v3.y);
        acc2.x += (v4.x + v5.x) + (v6.x + v7.x);
        acc2.y += (v4.y + v5.y) + (v6.y + v7.y);
    }
    for (; j < end; j++) {
        int s0 = g_csr[j];
        float2 v0 = *(const float2*)&g_h1a[(size_t)s0 * Hh + 2 * lane];
        acc.x += v0.x; acc.y += v0.y;
    }
    acc.x += acc2.x; acc.y += acc2.y;
    float d = g_dis[i];
    float2 bb = *(const float2*)&b1[2 * lane];
    acc.x = fmaxf(acc.x * d + bb.x, 0.f);
    acc.y = fmaxf(acc.y * d + bb.y, 0.f);
    *(float2*)&g_h1[(size_t)i * Hh + 2 * lane] = acc;
}

// GEMM2: x2a[N,40] = (h1[N,64] @ w2[64,40]) * dis.  2 rows/thread share ws loads.
__global__ void k_gemm2(const float* __restrict__ w2) {
    __shared__ float ws[Hh * Cc];
    __shared__ float hs[32][Hh];
    int tid = threadIdx.x;
    int row0 = blockIdx.x * 32;
    for (int i = tid; i < Hh * Cc; i += 640) ws[i] = w2[i];
    for (int i = tid; i < 32 * Hh; i += 640) {
        int r = i >> 6, k = i & 63;
        hs[r][k] = (row0 + r < Nn) ? g_h1[(size_t)(row0 + r) * Hh + k] : 0.f;
    }
    __syncthreads();
    int r = tid / Cc, c = tid % Cc;    // r: 0..15
    float accA = 0.f, accB = 0.f;
    #pragma unroll
    for (int k = 0; k < Hh; k++) {
        float b = ws[k * Cc + c];
        accA += hs[r][k] * b;
        accB += hs[r + 16][k] * b;
    }
    int rA = row0 + r, rB = row0 + r + 16;
    if (rA < Nn) g_x2a[(size_t)rA * Cc + c] = accA * g_dis[rA];
    if (rB < Nn) g_x2a[(size_t)rB * Cc + c] = accB * g_dis[rB];
}

// layer-2 aggregation + bias + log_softmax + row-normalize (bf16), fused. 8-deep MLP.
__global__ void k_gather2(const float* __restrict__ b2, float* __restrict__ out) {
    int i = blockIdx.x * 8 + (threadIdx.x >> 5);
    int lane = threadIdx.x & 31;
    if (i >= Nn) return;
    unsigned beg = g_off[i], end = g_off[i + 1];
    bool act = (lane < 20);
    size_t col = 2 * lane;
    float2 acc = make_float2(0.f, 0.f), acc2 = make_float2(0.f, 0.f);
    if (act) acc = *(const float2*)&g_x2a[(size_t)i * Cc + col];  // self term
    unsigned j = beg;
    for (; j + 8 <= end; j += 8) {
        int s0 = g_csr[j],     s1 = g_csr[j + 1], s2 = g_csr[j + 2], s3 = g_csr[j + 3];
        int s4 = g_csr[j + 4], s5 = g_csr[j + 5], s6 = g_csr[j + 6], s7 = g_csr[j + 7];
        if (act) {
            float2 v0 = *(const float2*)&g_x2a[(size_t)s0 * Cc + col];
            float2 v1 = *(const float2*)&g_x2a[(size_t)s1 * Cc + col];
            float2 v2 = *(const float2*)&g_x2a[(size_t)s2 * Cc + col];
            float2 v3 = *(const float2*)&g_x2a[(size_t)s3 * Cc + col];
            float2 v4 = *(const float2*)&g_x2a[(size_t)s4 * Cc + col];
            float2 v5 = *(const float2*)&g_x2a[(size_t)s5 * Cc + col];
            float2 v6 = *(const float2*)&g_x2a[(size_t)s6 * Cc + col];
            float2 v7 = *(const float2*)&g_x2a[(size_t)s7 * Cc + col];
            acc.x  += (v0.x + v1.x) + (v2.x + v3.x);
            acc.y  += (v0.y + v1.y) + (v2.y + v3.y);
            acc2.x += (v4.x + v5.x) + (v6.x + v7.x);
            acc2.y += (v4.y + v5.y) + (v6.y + v7.y);
        }
    }
    for (; j < end; j++) {
        int s0 = g_csr[j];
        if (act) {
            float2 v0 = *(const float2*)&g_x2a[(size_t)s0 * Cc + col];
            acc.x += v0.x; acc.y += v0.y;
        }
    }
    acc.x += acc2.x; acc.y += acc2.y;
    float d = g_dis[i];
    if (act) {
        float2 bb = *(const float2*)&b2[col];
        acc.x = acc.x * d + bb.x;
        acc.y = acc.y * d + bb.y;
    }
    // log_softmax
    float m = act ? fmaxf(acc.x, acc.y) : -3.4e38f;
    #pragma unroll
    for (int off = 16; off > 0; off >>= 1) m = fmaxf(m, __shfl_xor_sync(0xffffffffu, m, off));
    float s = act ? (expf(acc.x - m) + expf(acc.y - m)) : 0.f;
    #pragma unroll
    for (int off = 16; off > 0; off >>= 1) s += __shfl_xor_sync(0xffffffffu, s, off);
    float ls = m + logf(s);
    if (act) *(float2*)&out[(size_t)i * Cc + col] = make_float2(acc.x - ls, acc.y - ls);
    // normalized bf16 row for loss
    float ss = act ? (acc.x * acc.x + acc.y * acc.y) : 0.f;
    #pragma unroll
    for (int off = 16; off > 0; off >>= 1) ss += __shfl_xor_sync(0xffffffffu, ss, off);
    float inv = 1.0f / fmaxf(sqrtf(ss), 1e-8f);
    if (act) g_x2n[(size_t)i * 20 + lane] = __floats2bfloat162_rn(acc.x * inv, acc.y * inv);
}

// loss: persistent grid, warp per edge, 2-edge unroll.
#define LOSS_BLOCKS 2048
__global__ void k_loss(const int* __restrict__ src, const int* __restrict__ dst,
                       const float* __restrict__ ew, const float* __restrict__ lu) {
    __shared__ float sd[8];
    int wid = threadIdx.x >> 5, lane = threadIdx.x & 31;
    int warp_g = blockIdx.x * 8 + wid;
    int nwarp = LOSS_BLOCKS * 8;
    float thresh = g_thresh;
    bool act = (lane < 20);
    float acc = 0.f;
    int e = warp_g;
    for (; e + nwarp < Ee; e += 2 * nwarp) {
        int e2 = e + nwarp;
        int sA = src[e], dA = dst[e];
        int sB = src[e2], dB = dst[e2];
        float dotA = 0.f, dotB = 0.f;
        if (act) {
            float2 a0 = __bfloat1622float2(g_x2n[(size_t)sA * 20 + lane]);
            float2 b0 = __bfloat1622float2(g_x2n[(size_t)dA * 20 + lane]);
            float2 a1 = __bfloat1622float2(g_x2n[(size_t)sB * 20 + lane]);
            float2 b1 = __bfloat1622float2(g_x2n[(size_t)dB * 20 + lane]);
            dotA = a0.x * b0.x + a0.y * b0.y;
            dotB = a1.x * b1.x + a1.y * b1.y;
        }
        #pragma unroll
        for (int off = 16; off > 0; off >>= 1) {
            dotA += __shfl_xor_sync(0xffffffffu, dotA, off);
            dotB += __shfl_xor_sync(0xffffffffu, dotB, off);
        }
        if (lane == 0) {
            float wA = ew[e], wB = ew[e2];
            float csA = 1.0f - dotA, csB = 1.0f - dotB;
            bool mA = (wA >= thresh), mB = (wB >= thresh);
            acc += (mA ? wA : 1.0f - wA) * (mA ? csA : 1.0f - csA) * lu[e];
            acc += (mB ? wB : 1.0f - wB) * (mB ? csB : 1.0f - csB) * lu[e2];
        }
    }
    if (e < Ee) {
        int sA = src[e], dA = dst[e];
        float dotA = 0.f;
        if (act) {
            float2 a0 = __bfloat1622float2(g_x2n[(size_t)sA * 20 + lane]);
            float2 b0 = __bfloat1622float2(g_x2n[(size_t)dA * 20 + lane]);
            dotA = a0.x * b0.x + a0.y * b0.y;
        }
        #pragma unroll
        for (int off = 16; off > 0; off >>= 1) dotA += __shfl_xor_sync(0xffffffffu, dotA, off);
        if (lane == 0) {
            float wA = ew[e];
            float csA = 1.0f - dotA;
            bool mA = (wA >= thresh);
            acc += (mA ? wA : 1.0f - wA) * (mA ? csA : 1.0f - csA) * lu[e];
        }
    }
    if (lane == 0) sd[wid] = acc;
    __syncthreads();
    if (threadIdx.x == 0) {
        float t = 0.f;
        #pragma unroll
        for (int i = 0; i < 8; i++) t += sd[i];
        atomicAdd(&g_loss, (double)t);
    }
}

__global__ void k_final(float* __restrict__ out, int out_size) {
    if (out_size > Nn * Cc) out[Nn * Cc] = (float)(g_loss * (1.0 / (double)Ee));
}

// ---------------- launch ------------------------------------------------------

extern "C" void kernel_launch(void* const* d_in, const int* in_sizes, int n_in,
                              void* d_out, int out_size) {
    const float* x  = (const float*)d_in[0];
    const int*   ei = (const int*)d_in[1];
    const float* ew = (const float*)d_in[2];
    const float* lu = (const float*)d_in[3];
    const float* w1 = (const float*)d_in[4];
    const float* b1 = (const float*)d_in[5];
    const float* w2 = (const float*)d_in[6];
    const float* b2 = (const float*)d_in[7];
    const int* src = ei;
    const int* dst = ei + Ee;
    float* out = (float*)d_out;

    k_zero<<<256, 256>>>();                              // 0
    k_deg_hist<<<Ee / 4 / 256, 256>>>(dst, ew);          // 1
    k_scanP<<<PB, 1024>>>();                             // 2
    k_gemm1<<<(Nn + 255) / 256, 256>>>(x, w1);           // 3 <- profile slot (new 8x8 tile)
    k_csr_fill<<<Ee / 256, 256>>>(src, dst);             // 4
    k_scan<<<1, 1024>>>(0);                              // 5
    k_hist2<<<Ee / 4 / 256, 256>>>(ew);                  // 6
    k_scan<<<1, 1024>>>(1);                              // 7
    k_gather1<<<(Nn + 7) / 8, 256>>>(b1);                // 8
    k_gemm2<<<(Nn + 31) / 32, 640>>>(w2);                // 9
    k_gather2<<<(Nn + 7) / 8, 256>>>(b2, out);           // 10
    k_loss<<<LOSS_BLOCKS, 256>>>(src, dst, ew, lu);      // 11
    k_final<<<1, 1>>>(out, out_size);                    // 12
}